// round 3
// baseline (speedup 1.0000x reference)
#include <cuda_runtime.h>
#include <math.h>

// Problem constants
#define Dm   1024
#define Sm   4096
#define Bb   2
#define DIm  4096
#define NT   (Bb*Sm)       // 8192 token rows
#define KTOP 32
#define Am   64

// ---------------------------------------------------------------------------
// Scratch (static device globals: no allocation in kernel_launch)
// ---------------------------------------------------------------------------
__device__ float g_xn [NT*Dm];
__device__ float g_ma [NT*Dm];
__device__ float g_mb [NT*Dm];
__device__ float g_v  [NT*Dm];
__device__ float g_r  [NT*Dm];
__device__ float g_q  [NT*Am];
__device__ float g_k  [NT*Am];
__device__ float g_vsa[NT*Dm];
__device__ float g_att[NT*Dm];
__device__ float g_ao [NT*Dm];
__device__ float g_rkv[NT*Dm];
__device__ float g_x1 [NT*Dm];
__device__ float g_big[(size_t)NT*DIm];   // scores (B,S,S) then K2 (NT,DI): same size

// ---------------------------------------------------------------------------
// Generic NT SGEMM: C[m,n] = alpha * sum_k A[m,k]*Bw[n,k]  (+bias[n]) (relu^2) (+resid)
// BM=BN=64, BK=16, 256 threads, 4x4 per thread. Requires M%64==0, N%64==0, K%16==0.
// ---------------------------------------------------------------------------
__global__ void __launch_bounds__(256) sgemm_nt(
    const float* __restrict__ A, const float* __restrict__ Bw, float* __restrict__ C,
    int M, int N, int K, long sA, long sB, long sC,
    const float* __restrict__ bias, const float* __restrict__ resid,
    float alpha, int relu2)
{
    A  += (long)blockIdx.z * sA;
    Bw += (long)blockIdx.z * sB;
    C  += (long)blockIdx.z * sC;
    if (resid) resid += (long)blockIdx.z * sC;

    __shared__ float As[16][64];
    __shared__ float Bs[16][64];

    const int tid = threadIdx.x;
    const int tx = tid & 15, ty = tid >> 4;
    const int row0 = blockIdx.y * 64;
    const int col0 = blockIdx.x * 64;

    const int lr = tid >> 2;          // 0..63
    const int lk = (tid & 3) << 2;    // 0,4,8,12

    const float* Ap = A  + (long)(row0 + lr) * K + lk;
    const float* Bp = Bw + (long)(col0 + lr) * K + lk;

    float acc[4][4];
    #pragma unroll
    for (int i = 0; i < 4; i++)
        #pragma unroll
        for (int j = 0; j < 4; j++) acc[i][j] = 0.f;

    for (int k0 = 0; k0 < K; k0 += 16) {
        float4 a4 = *reinterpret_cast<const float4*>(Ap + k0);
        float4 b4 = *reinterpret_cast<const float4*>(Bp + k0);
        As[lk+0][lr] = a4.x; As[lk+1][lr] = a4.y; As[lk+2][lr] = a4.z; As[lk+3][lr] = a4.w;
        Bs[lk+0][lr] = b4.x; Bs[lk+1][lr] = b4.y; Bs[lk+2][lr] = b4.z; Bs[lk+3][lr] = b4.w;
        __syncthreads();
        #pragma unroll
        for (int kk = 0; kk < 16; kk++) {
            float4 av = *reinterpret_cast<const float4*>(&As[kk][ty << 2]);
            float4 bv = *reinterpret_cast<const float4*>(&Bs[kk][tx << 2]);
            float a_[4] = {av.x, av.y, av.z, av.w};
            float b_[4] = {bv.x, bv.y, bv.z, bv.w};
            #pragma unroll
            for (int i = 0; i < 4; i++)
                #pragma unroll
                for (int j = 0; j < 4; j++)
                    acc[i][j] += a_[i] * b_[j];
        }
        __syncthreads();
    }

    #pragma unroll
    for (int i = 0; i < 4; i++) {
        int r = row0 + (ty << 2) + i;
        #pragma unroll
        for (int j = 0; j < 4; j++) {
            int c = col0 + (tx << 2) + j;
            float v = acc[i][j] * alpha;
            if (bias)  v += bias[c];
            if (relu2) { v = fmaxf(v, 0.f); v *= v; }
            if (resid) v += resid[(long)r * N + c];
            C[(long)r * N + c] = v;
        }
    }
}

// ---------------------------------------------------------------------------
// rmsnorm: out = w * x / (||x||/sqrt(D) + 1e-8), one block per row
// ---------------------------------------------------------------------------
__global__ void __launch_bounds__(256) rmsnorm_k(
    const float* __restrict__ x, const float* __restrict__ w, float* __restrict__ out)
{
    int row = blockIdx.x;
    const float* xr = x + (long)row * Dm;
    int tid = threadIdx.x;
    float ss = 0.f;
    #pragma unroll
    for (int d = tid; d < Dm; d += 256) { float v = xr[d]; ss += v * v; }
    __shared__ float red[256];
    red[tid] = ss; __syncthreads();
    for (int o = 128; o; o >>= 1) {
        if (tid < o) red[tid] += red[tid + o];
        __syncthreads();
    }
    float scale = 1.f / (sqrtf(red[0] * (1.f / Dm)) + 1e-8f);
    #pragma unroll
    for (int d = tid; d < Dm; d += 256)
        out[(long)row * Dm + d] = w[d] * xr[d] * scale;
}

// ---------------------------------------------------------------------------
// token-shift mixes: o1 = xn*m1 + shift(xn)*(1-m1), o2 likewise with m2
// ---------------------------------------------------------------------------
__global__ void __launch_bounds__(256) mix2_k(
    const float* __restrict__ xn, const float* __restrict__ m1,
    const float* __restrict__ m2, float* __restrict__ o1, float* __restrict__ o2)
{
    long i = (long)blockIdx.x * 256 + threadIdx.x;
    int d = (int)(i & (Dm - 1));
    int s = (int)((i >> 10) & (Sm - 1));
    long pi = s ? (i - Dm) : i;           // first token shifts to itself
    float cur = xn[i], prev = xn[pi];
    float a = m1[d], b = m2[d];
    o1[i] = cur * a + prev * (1.f - a);
    o2[i] = cur * b + prev * (1.f - b);
}

// ---------------------------------------------------------------------------
// top-32 + softmax + V-gather, one block (128 thr) per query row
// ---------------------------------------------------------------------------
__global__ void __launch_bounds__(128) topk_attn_k(
    const float* __restrict__ Sc, const float* __restrict__ Vsa, float* __restrict__ Out)
{
    int q = blockIdx.x;          // 0..NT-1
    int b = q >> 12;             // /Sm
    const float* srow = Sc + (long)q * Sm;

    __shared__ float s[Sm];
    __shared__ float topv[KTOP];
    __shared__ int   topi[KTOP];
    __shared__ float wm[4];
    __shared__ int   wi[4];
    __shared__ float p[KTOP];

    int tid = threadIdx.x;
    for (int j = tid; j < Sm; j += 128) s[j] = srow[j];
    __syncthreads();

    for (int it = 0; it < KTOP; it++) {
        float best = -INFINITY; int bi = 0x7fffffff;
        for (int j = tid; j < Sm; j += 128) {
            float v = s[j];
            if (v > best) { best = v; bi = j; }   // first (= lowest index) wins ties
        }
        #pragma unroll
        for (int o = 16; o; o >>= 1) {
            float ov = __shfl_down_sync(0xffffffffu, best, o);
            int   oi = __shfl_down_sync(0xffffffffu, bi, o);
            if (ov > best || (ov == best && oi < bi)) { best = ov; bi = oi; }
        }
        if ((tid & 31) == 0) { wm[tid >> 5] = best; wi[tid >> 5] = bi; }
        __syncthreads();
        if (tid == 0) {
            float bb = wm[0]; int bj = wi[0];
            #pragma unroll
            for (int w2 = 1; w2 < 4; w2++)
                if (wm[w2] > bb || (wm[w2] == bb && wi[w2] < bj)) { bb = wm[w2]; bj = wi[w2]; }
            topv[it] = bb; topi[it] = bj;
            s[bj] = -INFINITY;
        }
        __syncthreads();
    }

    if (tid == 0) {
        float mx = topv[0], Z = 0.f;
        for (int i2 = 0; i2 < KTOP; i2++) { float e = expf(topv[i2] - mx); p[i2] = e; Z += e; }
        float iz = 1.f / Z;
        for (int i2 = 0; i2 < KTOP; i2++) p[i2] *= iz;
    }
    __syncthreads();

    const float* Vb = Vsa + (long)b * Sm * Dm;
    for (int d = tid; d < Dm; d += 128) {
        float acc = 0.f;
        #pragma unroll
        for (int i2 = 0; i2 < KTOP; i2++)
            acc += p[i2] * Vb[(long)topi[i2] * Dm + d];
        Out[(long)q * Dm + d] = acc;
    }
}

// ---------------------------------------------------------------------------
// elementwise gates
// ---------------------------------------------------------------------------
__global__ void __launch_bounds__(256) rkv_k(
    const float* __restrict__ r, const float* __restrict__ ao,
    const float* __restrict__ v, float* __restrict__ o)
{
    long i = (long)blockIdx.x * 256 + threadIdx.x;
    float sig = 1.f / (1.f + expf(-r[i]));
    o[i] = sig * (ao[i] + v[i]);
}

__global__ void __launch_bounds__(256) final_k(
    const float* __restrict__ x1, const float* __restrict__ r2,
    const float* __restrict__ kv, float* __restrict__ o)
{
    long i = (long)blockIdx.x * 256 + threadIdx.x;
    float sig = 1.f / (1.f + expf(-r2[i]));
    o[i] = x1[i] + sig * kv[i];
}

// ---------------------------------------------------------------------------
// launcher
// ---------------------------------------------------------------------------
extern "C" void kernel_launch(void* const* d_in, const int* in_sizes, int n_in,
                              void* d_out, int out_size)
{
    const float* x           = (const float*)d_in[0];
    const float* norm1_w     = (const float*)d_in[1];
    // d_in[2] tm_mix_k: feeds only tm_key_w path, whose result is unused
    const float* tm_mix_v    = (const float*)d_in[3];
    const float* tm_mix_r    = (const float*)d_in[4];
    // d_in[5] tm_key_w: DEAD in reference (k never consumed)
    const float* tm_value_w  = (const float*)d_in[6];
    const float* tm_recept_w = (const float*)d_in[7];
    const float* tm_out_w    = (const float*)d_in[8];
    const float* sa_q_w      = (const float*)d_in[9];
    const float* sa_q_b      = (const float*)d_in[10];
    const float* sa_k_w      = (const float*)d_in[11];
    const float* sa_k_b      = (const float*)d_in[12];
    const float* sa_v_w      = (const float*)d_in[13];
    const float* sa_v_b      = (const float*)d_in[14];
    const float* sa_o_w      = (const float*)d_in[15];
    const float* sa_o_b      = (const float*)d_in[16];
    const float* norm2_w     = (const float*)d_in[17];
    const float* cm_mix_k    = (const float*)d_in[18];
    const float* cm_mix_r    = (const float*)d_in[19];
    const float* cm_key_w    = (const float*)d_in[20];
    const float* cm_recept_w = (const float*)d_in[21];
    const float* cm_value_w  = (const float*)d_in[22];
    float* out = (float*)d_out;

    float *xn, *ma, *mb, *v, *r, *q, *kk, *vsa, *att, *ao, *rkv, *x1, *big;
    cudaGetSymbolAddress((void**)&xn,  g_xn);
    cudaGetSymbolAddress((void**)&ma,  g_ma);
    cudaGetSymbolAddress((void**)&mb,  g_mb);
    cudaGetSymbolAddress((void**)&v,   g_v);
    cudaGetSymbolAddress((void**)&r,   g_r);
    cudaGetSymbolAddress((void**)&q,   g_q);
    cudaGetSymbolAddress((void**)&kk,  g_k);
    cudaGetSymbolAddress((void**)&vsa, g_vsa);
    cudaGetSymbolAddress((void**)&att, g_att);
    cudaGetSymbolAddress((void**)&ao,  g_ao);
    cudaGetSymbolAddress((void**)&rkv, g_rkv);
    cudaGetSymbolAddress((void**)&x1,  g_x1);
    cudaGetSymbolAddress((void**)&big, g_big);

    const dim3 gD(Dm / 64, NT / 64);          // (16,128) for N=1024 GEMMs
    const dim3 gA(Am / 64, NT / 64);          // (1,128)  for N=64 GEMMs
    const dim3 gS(Sm / 64, Sm / 64, Bb);      // scores, batched
    const dim3 gDI(DIm / 64, NT / 64);        // (64,128) for N=4096
    const int  ewBlocks = NT * Dm / 256;

    // ---- time mix ----
    rmsnorm_k<<<NT, 256>>>(x, norm1_w, xn);
    mix2_k<<<ewBlocks, 256>>>(xn, tm_mix_v, tm_mix_r, ma, mb);
    sgemm_nt<<<gD, 256>>>(ma, tm_value_w,  v,  NT, Dm, Dm, 0, 0, 0, nullptr, nullptr, 1.f, 0);
    sgemm_nt<<<gD, 256>>>(mb, tm_recept_w, r,  NT, Dm, Dm, 0, 0, 0, nullptr, nullptr, 1.f, 0);
    sgemm_nt<<<gA, 256>>>(xn, sa_q_w, q,  NT, Am, Dm, 0, 0, 0, sa_q_b, nullptr, 1.f, 0);
    sgemm_nt<<<gA, 256>>>(xn, sa_k_w, kk, NT, Am, Dm, 0, 0, 0, sa_k_b, nullptr, 1.f, 0);
    sgemm_nt<<<gD, 256>>>(xn, sa_v_w, vsa, NT, Dm, Dm, 0, 0, 0, sa_v_b, nullptr, 1.f, 0);
    sgemm_nt<<<gS, 256>>>(q, kk, big, Sm, Sm, Am,
                          (long)Sm * Am, (long)Sm * Am, (long)Sm * Sm,
                          nullptr, nullptr, 0.125f, 0);   // / sqrt(64)
    topk_attn_k<<<NT, 128>>>(big, vsa, att);
    sgemm_nt<<<gD, 256>>>(att, sa_o_w, ao, NT, Dm, Dm, 0, 0, 0, sa_o_b, nullptr, 1.f, 0);
    rkv_k<<<ewBlocks, 256>>>(r, ao, v, rkv);
    sgemm_nt<<<gD, 256>>>(rkv, tm_out_w, x1, NT, Dm, Dm, 0, 0, 0, nullptr, x, 1.f, 0); // + residual x

    // ---- channel mix ----
    rmsnorm_k<<<NT, 256>>>(x1, norm2_w, xn);
    mix2_k<<<ewBlocks, 256>>>(xn, cm_mix_k, cm_mix_r, ma, mb);
    sgemm_nt<<<gDI, 256>>>(ma, cm_key_w, big, NT, DIm, Dm, 0, 0, 0, nullptr, nullptr, 1.f, 1); // relu^2
    sgemm_nt<<<gD, 256>>>(mb, cm_recept_w, r, NT, Dm, Dm, 0, 0, 0, nullptr, nullptr, 1.f, 0);
    sgemm_nt<<<gD, 256>>>(big, cm_value_w, v, NT, Dm, DIm, 0, 0, 0, nullptr, nullptr, 1.f, 0);
    final_k<<<ewBlocks, 256>>>(x1, r, v, out);
}

// round 4
// speedup vs baseline: 1.1029x; 1.1029x over previous
#include <cuda_runtime.h>
#include <math.h>

// Problem constants
#define Dm   1024
#define Sm   4096
#define Bb   2
#define DIm  4096
#define NT   (Bb*Sm)       // 8192 token rows
#define KTOP 32
#define Am   64

// ---------------------------------------------------------------------------
// Scratch (static device globals: no allocation in kernel_launch)
// ---------------------------------------------------------------------------
__device__ float g_xn [NT*Dm];
__device__ float g_ma [NT*Dm];
__device__ float g_mb [NT*Dm];
__device__ float g_v  [NT*Dm];
__device__ float g_r  [NT*Dm];
__device__ float g_q  [NT*Am];
__device__ float g_k  [NT*Am];
__device__ float g_vsa[NT*Dm];
__device__ float g_att[NT*Dm];
__device__ float g_ao [NT*Dm];
__device__ float g_rkv[NT*Dm];
__device__ float g_x1 [NT*Dm];
__device__ float g_big[(size_t)NT*DIm];   // scores (B,S,S) then K2 (NT,DI)

// ---------------------------------------------------------------------------
// Big NT SGEMM: 128x128 tile, BK=16, 256 threads, 8x8 microtile.
// C[m,n] = alpha * sum_k A[m,k]*Bw[n,k] (+bias[n]) (relu^2) (+resid)
// Requires M%128==0, N%128==0, K%16==0.
// ---------------------------------------------------------------------------
__global__ void __launch_bounds__(256, 2) sgemm_nt_big(
    const float* __restrict__ A, const float* __restrict__ Bw, float* __restrict__ C,
    int M, int N, int K, long sA, long sB, long sC,
    const float* __restrict__ bias, const float* __restrict__ resid,
    float alpha, int relu2)
{
    A  += (long)blockIdx.z * sA;
    Bw += (long)blockIdx.z * sB;
    C  += (long)blockIdx.z * sC;
    if (resid) resid += (long)blockIdx.z * sC;

    __shared__ float As[16][128];
    __shared__ float Bs[16][128];

    const int tid  = threadIdx.x;
    const int row0 = blockIdx.y * 128;
    const int col0 = blockIdx.x * 128;

    // loader mapping: each thread owns one row for A and one for B,
    // and two k-quads {lk0, lk0+8}. Warp = 32 consecutive rows at fixed
    // k-quad -> smem stores hit 32 distinct banks (conflict-free).
    const int lrow = tid & 127;
    const int lk0  = (tid >> 7) << 2;      // 0 or 4

    const float* Ap = A  + (long)(row0 + lrow) * K;
    const float* Bp = Bw + (long)(col0 + lrow) * K;

    // compute mapping: 8x8 per thread
    const int tx8 = (tid & 15) << 3;       // col fragment base
    const int ty8 = (tid >> 4) << 3;       // row fragment base

    float acc[8][8];
    #pragma unroll
    for (int i = 0; i < 8; i++)
        #pragma unroll
        for (int j = 0; j < 8; j++) acc[i][j] = 0.f;

    const int ktiles = K >> 4;
    float4 pa0, pa1, pb0, pb1;

    // prologue: load tile 0
    pa0 = *reinterpret_cast<const float4*>(Ap + lk0);
    pa1 = *reinterpret_cast<const float4*>(Ap + lk0 + 8);
    pb0 = *reinterpret_cast<const float4*>(Bp + lk0);
    pb1 = *reinterpret_cast<const float4*>(Bp + lk0 + 8);

    for (int t = 0; t < ktiles; t++) {
        // store staged tile
        As[lk0+0][lrow] = pa0.x; As[lk0+1][lrow] = pa0.y;
        As[lk0+2][lrow] = pa0.z; As[lk0+3][lrow] = pa0.w;
        As[lk0+8][lrow] = pa1.x; As[lk0+9][lrow] = pa1.y;
        As[lk0+10][lrow] = pa1.z; As[lk0+11][lrow] = pa1.w;
        Bs[lk0+0][lrow] = pb0.x; Bs[lk0+1][lrow] = pb0.y;
        Bs[lk0+2][lrow] = pb0.z; Bs[lk0+3][lrow] = pb0.w;
        Bs[lk0+8][lrow] = pb1.x; Bs[lk0+9][lrow] = pb1.y;
        Bs[lk0+10][lrow] = pb1.z; Bs[lk0+11][lrow] = pb1.w;
        __syncthreads();

        // prefetch next tile while computing
        if (t + 1 < ktiles) {
            const float* Apn = Ap + (t + 1) * 16;
            const float* Bpn = Bp + (t + 1) * 16;
            pa0 = *reinterpret_cast<const float4*>(Apn + lk0);
            pa1 = *reinterpret_cast<const float4*>(Apn + lk0 + 8);
            pb0 = *reinterpret_cast<const float4*>(Bpn + lk0);
            pb1 = *reinterpret_cast<const float4*>(Bpn + lk0 + 8);
        }

        #pragma unroll
        for (int kk = 0; kk < 16; kk++) {
            float4 a0 = *reinterpret_cast<const float4*>(&As[kk][ty8]);
            float4 a1 = *reinterpret_cast<const float4*>(&As[kk][ty8 + 4]);
            float4 b0 = *reinterpret_cast<const float4*>(&Bs[kk][tx8]);
            float4 b1 = *reinterpret_cast<const float4*>(&Bs[kk][tx8 + 4]);
            float a_[8] = {a0.x, a0.y, a0.z, a0.w, a1.x, a1.y, a1.z, a1.w};
            float b_[8] = {b0.x, b0.y, b0.z, b0.w, b1.x, b1.y, b1.z, b1.w};
            #pragma unroll
            for (int i = 0; i < 8; i++)
                #pragma unroll
                for (int j = 0; j < 8; j++)
                    acc[i][j] += a_[i] * b_[j];
        }
        __syncthreads();
    }

    // epilogue: 8x8 per thread, float4 stores
    #pragma unroll
    for (int i = 0; i < 8; i++) {
        int r = row0 + ty8 + i;
        float* crow = C + (long)r * N + col0 + tx8;
        const float* rrow = resid ? (resid + (long)r * N + col0 + tx8) : nullptr;
        float o[8];
        #pragma unroll
        for (int j = 0; j < 8; j++) {
            float v = acc[i][j] * alpha;
            if (bias)  v += bias[col0 + tx8 + j];
            if (relu2) { v = fmaxf(v, 0.f); v *= v; }
            if (rrow)  v += rrow[j];
            o[j] = v;
        }
        reinterpret_cast<float4*>(crow)[0] = make_float4(o[0], o[1], o[2], o[3]);
        reinterpret_cast<float4*>(crow)[1] = make_float4(o[4], o[5], o[6], o[7]);
    }
}

// ---------------------------------------------------------------------------
// Small SGEMM (kept for N=64 projections): 64x64, 4x4, BK=16
// ---------------------------------------------------------------------------
__global__ void __launch_bounds__(256) sgemm_nt(
    const float* __restrict__ A, const float* __restrict__ Bw, float* __restrict__ C,
    int M, int N, int K,
    const float* __restrict__ bias)
{
    __shared__ float As[16][64];
    __shared__ float Bs[16][64];

    const int tid = threadIdx.x;
    const int tx = tid & 15, ty = tid >> 4;
    const int row0 = blockIdx.y * 64;
    const int col0 = blockIdx.x * 64;

    const int lr = tid >> 2;
    const int lk = (tid & 3) << 2;

    const float* Ap = A  + (long)(row0 + lr) * K + lk;
    const float* Bp = Bw + (long)(col0 + lr) * K + lk;

    float acc[4][4];
    #pragma unroll
    for (int i = 0; i < 4; i++)
        #pragma unroll
        for (int j = 0; j < 4; j++) acc[i][j] = 0.f;

    for (int k0 = 0; k0 < K; k0 += 16) {
        float4 a4 = *reinterpret_cast<const float4*>(Ap + k0);
        float4 b4 = *reinterpret_cast<const float4*>(Bp + k0);
        As[lk+0][lr] = a4.x; As[lk+1][lr] = a4.y; As[lk+2][lr] = a4.z; As[lk+3][lr] = a4.w;
        Bs[lk+0][lr] = b4.x; Bs[lk+1][lr] = b4.y; Bs[lk+2][lr] = b4.z; Bs[lk+3][lr] = b4.w;
        __syncthreads();
        #pragma unroll
        for (int kk = 0; kk < 16; kk++) {
            float4 av = *reinterpret_cast<const float4*>(&As[kk][ty << 2]);
            float4 bv = *reinterpret_cast<const float4*>(&Bs[kk][tx << 2]);
            float a_[4] = {av.x, av.y, av.z, av.w};
            float b_[4] = {bv.x, bv.y, bv.z, bv.w};
            #pragma unroll
            for (int i = 0; i < 4; i++)
                #pragma unroll
                for (int j = 0; j < 4; j++)
                    acc[i][j] += a_[i] * b_[j];
        }
        __syncthreads();
    }

    #pragma unroll
    for (int i = 0; i < 4; i++) {
        int r = row0 + (ty << 2) + i;
        #pragma unroll
        for (int j = 0; j < 4; j++) {
            int c = col0 + (tx << 2) + j;
            float v = acc[i][j];
            if (bias) v += bias[c];
            C[(long)r * N + c] = v;
        }
    }
}

// ---------------------------------------------------------------------------
// rmsnorm
// ---------------------------------------------------------------------------
__global__ void __launch_bounds__(256) rmsnorm_k(
    const float* __restrict__ x, const float* __restrict__ w, float* __restrict__ out)
{
    int row = blockIdx.x;
    const float* xr = x + (long)row * Dm;
    int tid = threadIdx.x;
    float ss = 0.f;
    #pragma unroll
    for (int d = tid; d < Dm; d += 256) { float v = xr[d]; ss += v * v; }
    __shared__ float red[256];
    red[tid] = ss; __syncthreads();
    for (int o = 128; o; o >>= 1) {
        if (tid < o) red[tid] += red[tid + o];
        __syncthreads();
    }
    float scale = 1.f / (sqrtf(red[0] * (1.f / Dm)) + 1e-8f);
    #pragma unroll
    for (int d = tid; d < Dm; d += 256)
        out[(long)row * Dm + d] = w[d] * xr[d] * scale;
}

// ---------------------------------------------------------------------------
// token-shift mixes
// ---------------------------------------------------------------------------
__global__ void __launch_bounds__(256) mix2_k(
    const float* __restrict__ xn, const float* __restrict__ m1,
    const float* __restrict__ m2, float* __restrict__ o1, float* __restrict__ o2)
{
    long i = (long)blockIdx.x * 256 + threadIdx.x;
    int d = (int)(i & (Dm - 1));
    int s = (int)((i >> 10) & (Sm - 1));
    long pi = s ? (i - Dm) : i;
    float cur = xn[i], prev = xn[pi];
    float a = m1[d], b = m2[d];
    o1[i] = cur * a + prev * (1.f - a);
    o2[i] = cur * b + prev * (1.f - b);
}

// ---------------------------------------------------------------------------
// top-32 + softmax + V-gather
// ---------------------------------------------------------------------------
__global__ void __launch_bounds__(128) topk_attn_k(
    const float* __restrict__ Sc, const float* __restrict__ Vsa, float* __restrict__ Out)
{
    int q = blockIdx.x;
    int b = q >> 12;
    const float* srow = Sc + (long)q * Sm;

    __shared__ float s[Sm];
    __shared__ float topv[KTOP];
    __shared__ int   topi[KTOP];
    __shared__ float wm[4];
    __shared__ int   wi[4];
    __shared__ float p[KTOP];

    int tid = threadIdx.x;
    for (int j = tid; j < Sm; j += 128) s[j] = srow[j];
    __syncthreads();

    for (int it = 0; it < KTOP; it++) {
        float best = -INFINITY; int bi = 0x7fffffff;
        for (int j = tid; j < Sm; j += 128) {
            float v = s[j];
            if (v > best) { best = v; bi = j; }
        }
        #pragma unroll
        for (int o = 16; o; o >>= 1) {
            float ov = __shfl_down_sync(0xffffffffu, best, o);
            int   oi = __shfl_down_sync(0xffffffffu, bi, o);
            if (ov > best || (ov == best && oi < bi)) { best = ov; bi = oi; }
        }
        if ((tid & 31) == 0) { wm[tid >> 5] = best; wi[tid >> 5] = bi; }
        __syncthreads();
        if (tid == 0) {
            float bb = wm[0]; int bj = wi[0];
            #pragma unroll
            for (int w2 = 1; w2 < 4; w2++)
                if (wm[w2] > bb || (wm[w2] == bb && wi[w2] < bj)) { bb = wm[w2]; bj = wi[w2]; }
            topv[it] = bb; topi[it] = bj;
            s[bj] = -INFINITY;
        }
        __syncthreads();
    }

    if (tid == 0) {
        float mx = topv[0], Z = 0.f;
        for (int i2 = 0; i2 < KTOP; i2++) { float e = expf(topv[i2] - mx); p[i2] = e; Z += e; }
        float iz = 1.f / Z;
        for (int i2 = 0; i2 < KTOP; i2++) p[i2] *= iz;
    }
    __syncthreads();

    const float* Vb = Vsa + (long)b * Sm * Dm;
    for (int d = tid; d < Dm; d += 128) {
        float acc = 0.f;
        #pragma unroll
        for (int i2 = 0; i2 < KTOP; i2++)
            acc += p[i2] * Vb[(long)topi[i2] * Dm + d];
        Out[(long)q * Dm + d] = acc;
    }
}

// ---------------------------------------------------------------------------
// elementwise gates
// ---------------------------------------------------------------------------
__global__ void __launch_bounds__(256) rkv_k(
    const float* __restrict__ r, const float* __restrict__ ao,
    const float* __restrict__ v, float* __restrict__ o)
{
    long i = (long)blockIdx.x * 256 + threadIdx.x;
    float sig = 1.f / (1.f + expf(-r[i]));
    o[i] = sig * (ao[i] + v[i]);
}

__global__ void __launch_bounds__(256) final_k(
    const float* __restrict__ x1, const float* __restrict__ r2,
    const float* __restrict__ kv, float* __restrict__ o)
{
    long i = (long)blockIdx.x * 256 + threadIdx.x;
    float sig = 1.f / (1.f + expf(-r2[i]));
    o[i] = x1[i] + sig * kv[i];
}

// ---------------------------------------------------------------------------
// launcher
// ---------------------------------------------------------------------------
extern "C" void kernel_launch(void* const* d_in, const int* in_sizes, int n_in,
                              void* d_out, int out_size)
{
    const float* x           = (const float*)d_in[0];
    const float* norm1_w     = (const float*)d_in[1];
    const float* tm_mix_v    = (const float*)d_in[3];
    const float* tm_mix_r    = (const float*)d_in[4];
    // d_in[2]=tm_mix_k, d_in[5]=tm_key_w: dead in reference (k never consumed)
    const float* tm_value_w  = (const float*)d_in[6];
    const float* tm_recept_w = (const float*)d_in[7];
    const float* tm_out_w    = (const float*)d_in[8];
    const float* sa_q_w      = (const float*)d_in[9];
    const float* sa_q_b      = (const float*)d_in[10];
    const float* sa_k_w      = (const float*)d_in[11];
    const float* sa_k_b      = (const float*)d_in[12];
    const float* sa_v_w      = (const float*)d_in[13];
    const float* sa_v_b      = (const float*)d_in[14];
    const float* sa_o_w      = (const float*)d_in[15];
    const float* sa_o_b      = (const float*)d_in[16];
    const float* norm2_w     = (const float*)d_in[17];
    const float* cm_mix_k    = (const float*)d_in[18];
    const float* cm_mix_r    = (const float*)d_in[19];
    const float* cm_key_w    = (const float*)d_in[20];
    const float* cm_recept_w = (const float*)d_in[21];
    const float* cm_value_w  = (const float*)d_in[22];
    float* out = (float*)d_out;

    float *xn, *ma, *mb, *v, *r, *q, *kk, *vsa, *att, *ao, *rkv, *x1, *big;
    cudaGetSymbolAddress((void**)&xn,  g_xn);
    cudaGetSymbolAddress((void**)&ma,  g_ma);
    cudaGetSymbolAddress((void**)&mb,  g_mb);
    cudaGetSymbolAddress((void**)&v,   g_v);
    cudaGetSymbolAddress((void**)&r,   g_r);
    cudaGetSymbolAddress((void**)&q,   g_q);
    cudaGetSymbolAddress((void**)&kk,  g_k);
    cudaGetSymbolAddress((void**)&vsa, g_vsa);
    cudaGetSymbolAddress((void**)&att, g_att);
    cudaGetSymbolAddress((void**)&ao,  g_ao);
    cudaGetSymbolAddress((void**)&rkv, g_rkv);
    cudaGetSymbolAddress((void**)&x1,  g_x1);
    cudaGetSymbolAddress((void**)&big, g_big);

    const dim3 gD (Dm / 128,  NT / 128);        // (8, 64)
    const dim3 gA (Am / 64,   NT / 64);         // (1, 128) small kernel
    const dim3 gS (Sm / 128,  Sm / 128, Bb);    // (32, 32, 2)
    const dim3 gDI(DIm / 128, NT / 128);        // (32, 64)
    const int  ewBlocks = NT * Dm / 256;

    // ---- time mix ----
    rmsnorm_k<<<NT, 256>>>(x, norm1_w, xn);
    mix2_k<<<ewBlocks, 256>>>(xn, tm_mix_v, tm_mix_r, ma, mb);
    sgemm_nt_big<<<gD, 256>>>(ma, tm_value_w,  v,  NT, Dm, Dm, 0, 0, 0, nullptr, nullptr, 1.f, 0);
    sgemm_nt_big<<<gD, 256>>>(mb, tm_recept_w, r,  NT, Dm, Dm, 0, 0, 0, nullptr, nullptr, 1.f, 0);
    sgemm_nt<<<gA, 256>>>(xn, sa_q_w, q,  NT, Am, Dm, sa_q_b);
    sgemm_nt<<<gA, 256>>>(xn, sa_k_w, kk, NT, Am, Dm, sa_k_b);
    sgemm_nt_big<<<gD, 256>>>(xn, sa_v_w, vsa, NT, Dm, Dm, 0, 0, 0, sa_v_b, nullptr, 1.f, 0);
    sgemm_nt_big<<<gS, 256>>>(q, kk, big, Sm, Sm, Am,
                              (long)Sm * Am, (long)Sm * Am, (long)Sm * Sm,
                              nullptr, nullptr, 0.125f, 0);
    topk_attn_k<<<NT, 128>>>(big, vsa, att);
    sgemm_nt_big<<<gD, 256>>>(att, sa_o_w, ao, NT, Dm, Dm, 0, 0, 0, sa_o_b, nullptr, 1.f, 0);
    rkv_k<<<ewBlocks, 256>>>(r, ao, v, rkv);
    sgemm_nt_big<<<gD, 256>>>(rkv, tm_out_w, x1, NT, Dm, Dm, 0, 0, 0, nullptr, x, 1.f, 0);

    // ---- channel mix ----
    rmsnorm_k<<<NT, 256>>>(x1, norm2_w, xn);
    mix2_k<<<ewBlocks, 256>>>(xn, cm_mix_k, cm_mix_r, ma, mb);
    sgemm_nt_big<<<gDI, 256>>>(ma, cm_key_w, big, NT, DIm, Dm, 0, 0, 0, nullptr, nullptr, 1.f, 1);
    sgemm_nt_big<<<gD, 256>>>(mb, cm_recept_w, r, NT, Dm, Dm, 0, 0, 0, nullptr, nullptr, 1.f, 0);
    sgemm_nt_big<<<gD, 256>>>(big, cm_value_w, v, NT, Dm, DIm, 0, 0, 0, nullptr, nullptr, 1.f, 0);
    final_k<<<ewBlocks, 256>>>(x1, r, v, out);
}

// round 7
// speedup vs baseline: 2.8030x; 2.5415x over previous
#include <cuda_runtime.h>
#include <cuda_bf16.h>
#include <math.h>
#include <stdint.h>

// Problem constants
#define Dm   1024
#define Sm   4096
#define Bb   2
#define DIm  4096
#define NT   (Bb*Sm)       // 8192 token rows
#define KTOP 32
#define Am   64

// ---------------------------------------------------------------------------
// Scratch (static device globals)
// ---------------------------------------------------------------------------
__device__ float g_xn [NT*Dm];
__device__ float g_ma [NT*Dm];
__device__ float g_mb [NT*Dm];
__device__ float g_v  [NT*Dm];
__device__ float g_r  [NT*Dm];
__device__ float g_q  [NT*Am];
__device__ float g_k  [NT*Am];
__device__ float g_vsa[NT*Dm];
__device__ float g_att[NT*Dm];
__device__ float g_ao [NT*Dm];
__device__ float g_rkv[NT*Dm];
__device__ float g_x1 [NT*Dm];
__device__ float g_big[(size_t)NT*DIm];                              // scores / K2
__device__ __align__(16) __nv_bfloat16 g_apack[(size_t)NT*3*DIm];    // packed A
__device__ __align__(16) __nv_bfloat16 g_bpack[(size_t)DIm*3*Dm];    // packed B

// ---------------------------------------------------------------------------
// PTX helpers: cp.async + ldmatrix + mma.sync (all legal at compute_103)
// ---------------------------------------------------------------------------
__device__ __forceinline__ uint32_t smem_u32(const void* p) {
    uint32_t a;
    asm("{ .reg .u64 t; cvta.to.shared.u64 t, %1; cvt.u32.u64 %0, t; }" : "=r"(a) : "l"(p));
    return a;
}
__device__ __forceinline__ uint32_t sw128(uint32_t o) { return o ^ ((o >> 3) & 0x70); }

__device__ __forceinline__ void cp16(uint32_t s, const void* g) {
    asm volatile("cp.async.cg.shared.global [%0], [%1], 16;" :: "r"(s), "l"(g));
}
__device__ __forceinline__ void cp_commit() { asm volatile("cp.async.commit_group;" ::: "memory"); }
__device__ __forceinline__ void cp_wait0()  { asm volatile("cp.async.wait_group 0;" ::: "memory"); }
__device__ __forceinline__ void cp_wait1()  { asm volatile("cp.async.wait_group 1;" ::: "memory"); }

__device__ __forceinline__ void ldsm4(uint32_t* r, uint32_t a) {
    asm volatile("ldmatrix.sync.aligned.m8n8.x4.shared.b16 {%0,%1,%2,%3}, [%4];"
                 : "=r"(r[0]), "=r"(r[1]), "=r"(r[2]), "=r"(r[3]) : "r"(a));
}
__device__ __forceinline__ void ldsm2(uint32_t* r, uint32_t a) {
    asm volatile("ldmatrix.sync.aligned.m8n8.x2.shared.b16 {%0,%1}, [%2];"
                 : "=r"(r[0]), "=r"(r[1]) : "r"(a));
}
__device__ __forceinline__ void mma16816(float* c, const uint32_t* a, const uint32_t* b) {
    asm volatile(
        "mma.sync.aligned.m16n8k16.row.col.f32.bf16.bf16.f32 "
        "{%0,%1,%2,%3}, {%4,%5,%6,%7}, {%8,%9}, {%0,%1,%2,%3};"
        : "+f"(c[0]), "+f"(c[1]), "+f"(c[2]), "+f"(c[3])
        : "r"(a[0]), "r"(a[1]), "r"(a[2]), "r"(a[3]), "r"(b[0]), "r"(b[1]));
}

// ---------------------------------------------------------------------------
// mma.sync NT GEMM, split-bf16 operands.  C[m,n] = alpha*sum_k A'[m,k]B'[n,k]
// Tile: 128x128, BK=64 bf16, 256 threads (8 warps, 2x4), double-buffered
// cp.async. Requires M%128==0, N%128==0, Kp%64==0.
// ---------------------------------------------------------------------------
#define MG_SMEM 65536   // 2 stages x (16KB A + 16KB B)

__global__ void __launch_bounds__(256, 2) mma_gemm(
    const __nv_bfloat16* __restrict__ Ap, const __nv_bfloat16* __restrict__ Bp,
    float* __restrict__ C, int N, int Kp,
    long sA, long sB, long sC,
    const float* __restrict__ bias, const float* __restrict__ resid,
    float alpha, int relu2)
{
    extern __shared__ char smem[];
    Ap += (long)blockIdx.z * sA;
    Bp += (long)blockIdx.z * sB;
    C  += (long)blockIdx.z * sC;
    if (resid) resid += (long)blockIdx.z * sC;

    const int tid  = threadIdx.x;
    const int lane = tid & 31;
    const int wid  = tid >> 5;
    const int wm   = wid >> 2;           // 0..1 : 64-row band
    const int wn   = wid & 3;            // 0..3 : 32-col band
    const int row0 = blockIdx.y * 128;
    const int col0 = blockIdx.x * 128;
    const uint32_t su = smem_u32(smem);

    float acc[4][4][4];
    #pragma unroll
    for (int mt = 0; mt < 4; mt++)
        #pragma unroll
        for (int nt = 0; nt < 4; nt++)
            #pragma unroll
            for (int i = 0; i < 4; i++) acc[mt][nt][i] = 0.f;

    const int nch = Kp >> 6;

    auto load_stage = [&](uint32_t sbase, int k0) {
        #pragma unroll
        for (int i = 0; i < 4; i++) {
            int j = tid + 256 * i;
            int r = j >> 3, cb = (j & 7) << 4;          // byte col
            cp16(sbase + sw128((uint32_t)(r * 128 + cb)),
                 Ap + (long)(row0 + r) * Kp + k0 + (cb >> 1));
        }
        #pragma unroll
        for (int i = 0; i < 4; i++) {
            int j = tid + 256 * i;
            int r = j >> 3, cb = (j & 7) << 4;
            cp16(sbase + 16384u + sw128((uint32_t)(r * 128 + cb)),
                 Bp + (long)(col0 + r) * Kp + k0 + (cb >> 1));
        }
    };

    load_stage(su, 0);
    cp_commit();

    for (int t = 0; t < nch; t++) {
        if (t + 1 < nch) {
            load_stage(su + (uint32_t)(((t + 1) & 1) << 15), (t + 1) << 6);
            cp_commit();
            cp_wait1();
        } else {
            cp_wait0();
        }
        __syncthreads();

        const uint32_t sAb = su + (uint32_t)((t & 1) << 15);
        const uint32_t sBb = sAb + 16384u;

        #pragma unroll
        for (int ks = 0; ks < 4; ks++) {
            uint32_t a[4][4], b[4][2];
            #pragma unroll
            for (int mt = 0; mt < 4; mt++) {
                uint32_t off = (uint32_t)((wm * 64 + mt * 16 + (lane & 15)) * 128
                                          + ks * 32 + ((lane >> 4) << 4));
                ldsm4(a[mt], sAb + sw128(off));
            }
            #pragma unroll
            for (int nt = 0; nt < 4; nt++) {
                uint32_t off = (uint32_t)((wn * 32 + nt * 8 + (lane & 7)) * 128
                                          + ks * 32 + (((lane >> 3) & 1) << 4));
                ldsm2(b[nt], sBb + sw128(off));
            }
            #pragma unroll
            for (int mt = 0; mt < 4; mt++)
                #pragma unroll
                for (int nt = 0; nt < 4; nt++)
                    mma16816(acc[mt][nt], a[mt], b[nt]);
        }
        __syncthreads();
    }

    // epilogue: direct register -> global, float2 per half-tile
    #pragma unroll
    for (int mt = 0; mt < 4; mt++) {
        int gr0 = row0 + wm * 64 + mt * 16 + (lane >> 2);
        #pragma unroll
        for (int nt = 0; nt < 4; nt++) {
            int gc = col0 + wn * 32 + nt * 8 + ((lane & 3) << 1);
            float b0 = 0.f, b1 = 0.f;
            if (bias) { b0 = bias[gc]; b1 = bias[gc + 1]; }
            #pragma unroll
            for (int h = 0; h < 2; h++) {
                int gr = gr0 + h * 8;
                float v0 = acc[mt][nt][h * 2 + 0] * alpha + b0;
                float v1 = acc[mt][nt][h * 2 + 1] * alpha + b1;
                if (relu2) { v0 = fmaxf(v0, 0.f); v0 *= v0;
                             v1 = fmaxf(v1, 0.f); v1 *= v1; }
                if (resid) {
                    float2 rr = *reinterpret_cast<const float2*>(resid + (long)gr * N + gc);
                    v0 += rr.x; v1 += rr.y;
                }
                *reinterpret_cast<float2*>(C + (long)gr * N + gc) = make_float2(v0, v1);
            }
        }
    }
}

// ---------------------------------------------------------------------------
// split-bf16 pack: A-mode -> [hi|hi|lo], B-mode -> [hi|lo|hi] along K (x3)
// ---------------------------------------------------------------------------
__global__ void __launch_bounds__(256) split_pack(
    const float* __restrict__ src, __nv_bfloat16* __restrict__ dst,
    int K, long total2, int modeB)
{
    long i = (long)blockIdx.x * 256 + threadIdx.x;
    if (i >= total2) return;
    const int K2 = K >> 1;
    long m = i / K2;
    int  k = (int)(i - m * K2) << 1;
    float2 x = *reinterpret_cast<const float2*>(src + m * K + k);
    __nv_bfloat16 h0 = __float2bfloat16_rn(x.x);
    __nv_bfloat16 h1 = __float2bfloat16_rn(x.y);
    __nv_bfloat16 l0 = __float2bfloat16_rn(x.x - __bfloat162float(h0));
    __nv_bfloat16 l1 = __float2bfloat16_rn(x.y - __bfloat162float(h1));
    __nv_bfloat162 hp; hp.x = h0; hp.y = h1;
    __nv_bfloat162 lp; lp.x = l0; lp.y = l1;
    long base = m * 3L * K;
    *reinterpret_cast<__nv_bfloat162*>(dst + base + k) = hp;
    if (modeB) {
        *reinterpret_cast<__nv_bfloat162*>(dst + base + K + k)     = lp;
        *reinterpret_cast<__nv_bfloat162*>(dst + base + 2 * K + k) = hp;
    } else {
        *reinterpret_cast<__nv_bfloat162*>(dst + base + K + k)     = hp;
        *reinterpret_cast<__nv_bfloat162*>(dst + base + 2 * K + k) = lp;
    }
}

// ---------------------------------------------------------------------------
// Small SIMT SGEMM for N=64 projections (q, k)
// ---------------------------------------------------------------------------
__global__ void __launch_bounds__(256) sgemm_nt(
    const float* __restrict__ A, const float* __restrict__ Bw, float* __restrict__ C,
    int M, int N, int K, const float* __restrict__ bias)
{
    __shared__ float As[16][64];
    __shared__ float Bs[16][64];
    const int tid = threadIdx.x;
    const int tx = tid & 15, ty = tid >> 4;
    const int row0 = blockIdx.y * 64;
    const int col0 = blockIdx.x * 64;
    const int lr = tid >> 2;
    const int lk = (tid & 3) << 2;
    const float* Apt = A  + (long)(row0 + lr) * K + lk;
    const float* Bpt = Bw + (long)(col0 + lr) * K + lk;
    float acc[4][4];
    #pragma unroll
    for (int i = 0; i < 4; i++)
        #pragma unroll
        for (int j = 0; j < 4; j++) acc[i][j] = 0.f;
    for (int k0 = 0; k0 < K; k0 += 16) {
        float4 a4 = *reinterpret_cast<const float4*>(Apt + k0);
        float4 b4 = *reinterpret_cast<const float4*>(Bpt + k0);
        As[lk+0][lr] = a4.x; As[lk+1][lr] = a4.y; As[lk+2][lr] = a4.z; As[lk+3][lr] = a4.w;
        Bs[lk+0][lr] = b4.x; Bs[lk+1][lr] = b4.y; Bs[lk+2][lr] = b4.z; Bs[lk+3][lr] = b4.w;
        __syncthreads();
        #pragma unroll
        for (int kk = 0; kk < 16; kk++) {
            float4 av = *reinterpret_cast<const float4*>(&As[kk][ty << 2]);
            float4 bv = *reinterpret_cast<const float4*>(&Bs[kk][tx << 2]);
            float a_[4] = {av.x, av.y, av.z, av.w};
            float b_[4] = {bv.x, bv.y, bv.z, bv.w};
            #pragma unroll
            for (int i = 0; i < 4; i++)
                #pragma unroll
                for (int j = 0; j < 4; j++)
                    acc[i][j] += a_[i] * b_[j];
        }
        __syncthreads();
    }
    #pragma unroll
    for (int i = 0; i < 4; i++) {
        int r = row0 + (ty << 2) + i;
        #pragma unroll
        for (int j = 0; j < 4; j++) {
            int c = col0 + (tx << 2) + j;
            float v = acc[i][j];
            if (bias) v += bias[c];
            C[(long)r * N + c] = v;
        }
    }
}

// ---------------------------------------------------------------------------
// rmsnorm / mixes / topk / gates
// ---------------------------------------------------------------------------
__global__ void __launch_bounds__(256) rmsnorm_k(
    const float* __restrict__ x, const float* __restrict__ w, float* __restrict__ out)
{
    int row = blockIdx.x;
    const float* xr = x + (long)row * Dm;
    int tid = threadIdx.x;
    float ss = 0.f;
    #pragma unroll
    for (int d = tid; d < Dm; d += 256) { float v = xr[d]; ss += v * v; }
    __shared__ float red[256];
    red[tid] = ss; __syncthreads();
    for (int o = 128; o; o >>= 1) {
        if (tid < o) red[tid] += red[tid + o];
        __syncthreads();
    }
    float scale = 1.f / (sqrtf(red[0] * (1.f / Dm)) + 1e-8f);
    #pragma unroll
    for (int d = tid; d < Dm; d += 256)
        out[(long)row * Dm + d] = w[d] * xr[d] * scale;
}

__global__ void __launch_bounds__(256) mix2_k(
    const float* __restrict__ xn, const float* __restrict__ m1,
    const float* __restrict__ m2, float* __restrict__ o1, float* __restrict__ o2)
{
    long i = (long)blockIdx.x * 256 + threadIdx.x;
    int d = (int)(i & (Dm - 1));
    int s = (int)((i >> 10) & (Sm - 1));
    long pi = s ? (i - Dm) : i;
    float cur = xn[i], prev = xn[pi];
    float a = m1[d], b = m2[d];
    o1[i] = cur * a + prev * (1.f - a);
    o2[i] = cur * b + prev * (1.f - b);
}

__global__ void __launch_bounds__(128) topk_attn_k(
    const float* __restrict__ Sc, const float* __restrict__ Vsa, float* __restrict__ Out)
{
    int q = blockIdx.x;
    int b = q >> 12;
    const float* srow = Sc + (long)q * Sm;
    __shared__ float s[Sm];
    __shared__ float topv[KTOP];
    __shared__ int   topi[KTOP];
    __shared__ float wm[4];
    __shared__ int   wi[4];
    __shared__ float p[KTOP];
    int tid = threadIdx.x;
    for (int j = tid; j < Sm; j += 128) s[j] = srow[j];
    __syncthreads();
    for (int it = 0; it < KTOP; it++) {
        float best = -INFINITY; int bi = 0x7fffffff;
        for (int j = tid; j < Sm; j += 128) {
            float v = s[j];
            if (v > best) { best = v; bi = j; }
        }
        #pragma unroll
        for (int o = 16; o; o >>= 1) {
            float ov = __shfl_down_sync(0xffffffffu, best, o);
            int   oi = __shfl_down_sync(0xffffffffu, bi, o);
            if (ov > best || (ov == best && oi < bi)) { best = ov; bi = oi; }
        }
        if ((tid & 31) == 0) { wm[tid >> 5] = best; wi[tid >> 5] = bi; }
        __syncthreads();
        if (tid == 0) {
            float bb = wm[0]; int bj = wi[0];
            #pragma unroll
            for (int w2 = 1; w2 < 4; w2++)
                if (wm[w2] > bb || (wm[w2] == bb && wi[w2] < bj)) { bb = wm[w2]; bj = wi[w2]; }
            topv[it] = bb; topi[it] = bj;
            s[bj] = -INFINITY;
        }
        __syncthreads();
    }
    if (tid == 0) {
        float mx = topv[0], Z = 0.f;
        for (int i2 = 0; i2 < KTOP; i2++) { float e = expf(topv[i2] - mx); p[i2] = e; Z += e; }
        float iz = 1.f / Z;
        for (int i2 = 0; i2 < KTOP; i2++) p[i2] *= iz;
    }
    __syncthreads();
    const float* Vb = Vsa + (long)b * Sm * Dm;
    for (int d = tid; d < Dm; d += 128) {
        float acc = 0.f;
        #pragma unroll
        for (int i2 = 0; i2 < KTOP; i2++)
            acc += p[i2] * Vb[(long)topi[i2] * Dm + d];
        Out[(long)q * Dm + d] = acc;
    }
}

__global__ void __launch_bounds__(256) rkv_k(
    const float* __restrict__ r, const float* __restrict__ ao,
    const float* __restrict__ v, float* __restrict__ o)
{
    long i = (long)blockIdx.x * 256 + threadIdx.x;
    float sig = 1.f / (1.f + expf(-r[i]));
    o[i] = sig * (ao[i] + v[i]);
}

__global__ void __launch_bounds__(256) final_k(
    const float* __restrict__ x1, const float* __restrict__ r2,
    const float* __restrict__ kv, float* __restrict__ o)
{
    long i = (long)blockIdx.x * 256 + threadIdx.x;
    float sig = 1.f / (1.f + expf(-r2[i]));
    o[i] = x1[i] + sig * kv[i];
}

// ---------------------------------------------------------------------------
// launcher
// ---------------------------------------------------------------------------
static void pack_pair(const float* Asrc, int Ka, long Mrows,
                      const float* Bsrc, int Kb, long Nrows,
                      __nv_bfloat16* ap, __nv_bfloat16* bp)
{
    long ta = Mrows * Ka / 2;
    long tb = Nrows * Kb / 2;
    split_pack<<<(unsigned)((ta + 255) / 256), 256>>>(Asrc, ap, Ka, ta, 0);
    split_pack<<<(unsigned)((tb + 255) / 256), 256>>>(Bsrc, bp, Kb, tb, 1);
}

extern "C" void kernel_launch(void* const* d_in, const int* in_sizes, int n_in,
                              void* d_out, int out_size)
{
    const float* x           = (const float*)d_in[0];
    const float* norm1_w     = (const float*)d_in[1];
    const float* tm_mix_v    = (const float*)d_in[3];
    const float* tm_mix_r    = (const float*)d_in[4];
    // d_in[2]=tm_mix_k, d_in[5]=tm_key_w: dead in reference
    const float* tm_value_w  = (const float*)d_in[6];
    const float* tm_recept_w = (const float*)d_in[7];
    const float* tm_out_w    = (const float*)d_in[8];
    const float* sa_q_w      = (const float*)d_in[9];
    const float* sa_q_b      = (const float*)d_in[10];
    const float* sa_k_w      = (const float*)d_in[11];
    const float* sa_k_b      = (const float*)d_in[12];
    const float* sa_v_w      = (const float*)d_in[13];
    const float* sa_v_b      = (const float*)d_in[14];
    const float* sa_o_w      = (const float*)d_in[15];
    const float* sa_o_b      = (const float*)d_in[16];
    const float* norm2_w     = (const float*)d_in[17];
    const float* cm_mix_k    = (const float*)d_in[18];
    const float* cm_mix_r    = (const float*)d_in[19];
    const float* cm_key_w    = (const float*)d_in[20];
    const float* cm_recept_w = (const float*)d_in[21];
    const float* cm_value_w  = (const float*)d_in[22];
    float* out = (float*)d_out;

    float *xn, *ma, *mb, *v, *r, *q, *kk, *vsa, *att, *ao, *rkv, *x1, *big;
    __nv_bfloat16 *ap, *bp;
    cudaGetSymbolAddress((void**)&xn,  g_xn);
    cudaGetSymbolAddress((void**)&ma,  g_ma);
    cudaGetSymbolAddress((void**)&mb,  g_mb);
    cudaGetSymbolAddress((void**)&v,   g_v);
    cudaGetSymbolAddress((void**)&r,   g_r);
    cudaGetSymbolAddress((void**)&q,   g_q);
    cudaGetSymbolAddress((void**)&kk,  g_k);
    cudaGetSymbolAddress((void**)&vsa, g_vsa);
    cudaGetSymbolAddress((void**)&att, g_att);
    cudaGetSymbolAddress((void**)&ao,  g_ao);
    cudaGetSymbolAddress((void**)&rkv, g_rkv);
    cudaGetSymbolAddress((void**)&x1,  g_x1);
    cudaGetSymbolAddress((void**)&big, g_big);
    cudaGetSymbolAddress((void**)&ap,  g_apack);
    cudaGetSymbolAddress((void**)&bp,  g_bpack);

    cudaFuncSetAttribute(mma_gemm, cudaFuncAttributeMaxDynamicSharedMemorySize, MG_SMEM);

    const dim3 gD (Dm / 128,  NT / 128);          // (8, 64)   N=1024
    const dim3 gDI(DIm / 128, NT / 128);          // (32, 64)  N=4096
    const dim3 gS (Sm / 128,  Sm / 128, Bb);      // (32, 32, 2) scores
    const dim3 gA (Am / 64,   NT / 64);           // small q/k
    const int  ewBlocks = NT * Dm / 256;
    const int  Kp1 = 3 * Dm;                      // 3072
    const int  Kp4 = 3 * DIm;                     // 12288
    const int  KpS = 3 * Am;                      // 192

    // ---- time mix ----
    rmsnorm_k<<<NT, 256>>>(x, norm1_w, xn);
    mix2_k<<<ewBlocks, 256>>>(xn, tm_mix_v, tm_mix_r, ma, mb);

    pack_pair(ma, Dm, NT, tm_value_w, Dm, Dm, ap, bp);
    mma_gemm<<<gD, 256, MG_SMEM>>>(ap, bp, v, Dm, Kp1, 0, 0, 0, nullptr, nullptr, 1.f, 0);

    pack_pair(mb, Dm, NT, tm_recept_w, Dm, Dm, ap, bp);
    mma_gemm<<<gD, 256, MG_SMEM>>>(ap, bp, r, Dm, Kp1, 0, 0, 0, nullptr, nullptr, 1.f, 0);

    sgemm_nt<<<gA, 256>>>(xn, sa_q_w, q,  NT, Am, Dm, sa_q_b);
    sgemm_nt<<<gA, 256>>>(xn, sa_k_w, kk, NT, Am, Dm, sa_k_b);

    pack_pair(xn, Dm, NT, sa_v_w, Dm, Dm, ap, bp);
    mma_gemm<<<gD, 256, MG_SMEM>>>(ap, bp, vsa, Dm, Kp1, 0, 0, 0, sa_v_b, nullptr, 1.f, 0);

    pack_pair(q, Am, NT, kk, Am, NT, ap, bp);
    mma_gemm<<<gS, 256, MG_SMEM>>>(ap, bp, big, Sm, KpS,
                                   (long)Sm * KpS, (long)Sm * KpS, (long)Sm * Sm,
                                   nullptr, nullptr, 0.125f, 0);

    topk_attn_k<<<NT, 128>>>(big, vsa, att);

    pack_pair(att, Dm, NT, sa_o_w, Dm, Dm, ap, bp);
    mma_gemm<<<gD, 256, MG_SMEM>>>(ap, bp, ao, Dm, Kp1, 0, 0, 0, sa_o_b, nullptr, 1.f, 0);

    rkv_k<<<ewBlocks, 256>>>(r, ao, v, rkv);

    pack_pair(rkv, Dm, NT, tm_out_w, Dm, Dm, ap, bp);
    mma_gemm<<<gD, 256, MG_SMEM>>>(ap, bp, x1, Dm, Kp1, 0, 0, 0, nullptr, x, 1.f, 0);

    // ---- channel mix ----
    rmsnorm_k<<<NT, 256>>>(x1, norm2_w, xn);
    mix2_k<<<ewBlocks, 256>>>(xn, cm_mix_k, cm_mix_r, ma, mb);

    pack_pair(ma, Dm, NT, cm_key_w, Dm, DIm, ap, bp);
    mma_gemm<<<gDI, 256, MG_SMEM>>>(ap, bp, big, DIm, Kp1, 0, 0, 0, nullptr, nullptr, 1.f, 1);

    pack_pair(mb, Dm, NT, cm_recept_w, Dm, Dm, ap, bp);
    mma_gemm<<<gD, 256, MG_SMEM>>>(ap, bp, r, Dm, Kp1, 0, 0, 0, nullptr, nullptr, 1.f, 0);

    pack_pair(big, DIm, NT, cm_value_w, DIm, Dm, ap, bp);
    mma_gemm<<<gD, 256, MG_SMEM>>>(ap, bp, v, Dm, Kp4, 0, 0, 0, nullptr, nullptr, 1.f, 0);

    final_k<<<ewBlocks, 256>>>(x1, r, v, out);
}

// round 8
// speedup vs baseline: 3.0269x; 1.0799x over previous
#include <cuda_runtime.h>
#include <cuda_bf16.h>
#include <math.h>
#include <stdint.h>

// Problem constants
#define Dm   1024
#define Sm   4096
#define Bb   2
#define DIm  4096
#define NT   (Bb*Sm)       // 8192 token rows
#define KTOP 32
#define Am   64

// ---------------------------------------------------------------------------
// Scratch (static device globals)
// ---------------------------------------------------------------------------
__device__ float g_xn [NT*Dm];
__device__ float g_v  [NT*Dm];
__device__ float g_r  [NT*Dm];
__device__ float g_q  [NT*Am];
__device__ float g_k  [NT*Am];
__device__ float g_vsa[NT*Dm];
__device__ float g_ao [NT*Dm];
__device__ float g_x1 [NT*Dm];
__device__ float g_big[(size_t)NT*Sm];                               // scores
__device__ __align__(16) __nv_bfloat16 g_pA1 [(size_t)NT*3*Dm];      // packed A #1
__device__ __align__(16) __nv_bfloat16 g_pA2 [(size_t)NT*3*Dm];      // packed A #2
__device__ __align__(16) __nv_bfloat16 g_pXN [(size_t)NT*3*Dm];      // packed xn
__device__ __align__(16) __nv_bfloat16 g_pBIG[(size_t)NT*3*DIm];     // packed k2
__device__ __align__(16) __nv_bfloat16 g_pQ  [(size_t)NT*3*Am];
__device__ __align__(16) __nv_bfloat16 g_pK  [(size_t)NT*3*Am];
__device__ __align__(16) __nv_bfloat16 g_wpk [(size_t)DIm*3*DIm/4];  // weight pack (max 1024x12288)

// ---------------------------------------------------------------------------
// PTX helpers: cp.async + ldmatrix + mma.sync (legal at compute_103)
// ---------------------------------------------------------------------------
__device__ __forceinline__ uint32_t smem_u32(const void* p) {
    uint32_t a;
    asm("{ .reg .u64 t; cvta.to.shared.u64 t, %1; cvt.u32.u64 %0, t; }" : "=r"(a) : "l"(p));
    return a;
}
__device__ __forceinline__ uint32_t sw128(uint32_t o) { return o ^ ((o >> 3) & 0x70); }

__device__ __forceinline__ void cp16(uint32_t s, const void* g) {
    asm volatile("cp.async.cg.shared.global [%0], [%1], 16;" :: "r"(s), "l"(g));
}
__device__ __forceinline__ void cp_commit() { asm volatile("cp.async.commit_group;" ::: "memory"); }
__device__ __forceinline__ void cp_wait0()  { asm volatile("cp.async.wait_group 0;" ::: "memory"); }
__device__ __forceinline__ void cp_wait1()  { asm volatile("cp.async.wait_group 1;" ::: "memory"); }

__device__ __forceinline__ void ldsm4(uint32_t* r, uint32_t a) {
    asm volatile("ldmatrix.sync.aligned.m8n8.x4.shared.b16 {%0,%1,%2,%3}, [%4];"
                 : "=r"(r[0]), "=r"(r[1]), "=r"(r[2]), "=r"(r[3]) : "r"(a));
}
__device__ __forceinline__ void ldsm2(uint32_t* r, uint32_t a) {
    asm volatile("ldmatrix.sync.aligned.m8n8.x2.shared.b16 {%0,%1}, [%2];"
                 : "=r"(r[0]), "=r"(r[1]) : "r"(a));
}
__device__ __forceinline__ void mma16816(float* c, const uint32_t* a, const uint32_t* b) {
    asm volatile(
        "mma.sync.aligned.m16n8k16.row.col.f32.bf16.bf16.f32 "
        "{%0,%1,%2,%3}, {%4,%5,%6,%7}, {%8,%9}, {%0,%1,%2,%3};"
        : "+f"(c[0]), "+f"(c[1]), "+f"(c[2]), "+f"(c[3])
        : "r"(a[0]), "r"(a[1]), "r"(a[2]), "r"(a[3]), "r"(b[0]), "r"(b[1]));
}

__device__ __forceinline__ void split2(float v0, float v1,
                                       __nv_bfloat162& hp, __nv_bfloat162& lp) {
    __nv_bfloat16 h0 = __float2bfloat16_rn(v0);
    __nv_bfloat16 h1 = __float2bfloat16_rn(v1);
    __nv_bfloat16 l0 = __float2bfloat16_rn(v0 - __bfloat162float(h0));
    __nv_bfloat16 l1 = __float2bfloat16_rn(v1 - __bfloat162float(h1));
    hp.x = h0; hp.y = h1; lp.x = l0; lp.y = l1;
}

// ---------------------------------------------------------------------------
// mma.sync NT GEMM, split-bf16 operands.  Tile 128x128, BK=64, 256 threads.
// packout!=0: write split-bf16 A-pack triplets [hi|hi|lo] (row stride 3N)
// ---------------------------------------------------------------------------
#define MG_SMEM 65536   // 2 stages x (16KB A + 16KB B)

__global__ void __launch_bounds__(256, 2) mma_gemm(
    const __nv_bfloat16* __restrict__ Ap, const __nv_bfloat16* __restrict__ Bp,
    float* __restrict__ C, int N, int Kp,
    long sA, long sB, long sC,
    const float* __restrict__ bias, const float* __restrict__ resid,
    float alpha, int relu2, int packout)
{
    extern __shared__ char smem[];
    Ap += (long)blockIdx.z * sA;
    Bp += (long)blockIdx.z * sB;
    C  += (long)blockIdx.z * sC;
    if (resid) resid += (long)blockIdx.z * sC;

    const int tid  = threadIdx.x;
    const int lane = tid & 31;
    const int wid  = tid >> 5;
    const int wm   = wid >> 2;
    const int wn   = wid & 3;
    const int row0 = blockIdx.y * 128;
    const int col0 = blockIdx.x * 128;
    const uint32_t su = smem_u32(smem);

    float acc[4][4][4];
    #pragma unroll
    for (int mt = 0; mt < 4; mt++)
        #pragma unroll
        for (int nt = 0; nt < 4; nt++)
            #pragma unroll
            for (int i = 0; i < 4; i++) acc[mt][nt][i] = 0.f;

    const int nch = Kp >> 6;

    auto load_stage = [&](uint32_t sbase, int k0) {
        #pragma unroll
        for (int i = 0; i < 4; i++) {
            int j = tid + 256 * i;
            int r = j >> 3, cb = (j & 7) << 4;
            cp16(sbase + sw128((uint32_t)(r * 128 + cb)),
                 Ap + (long)(row0 + r) * Kp + k0 + (cb >> 1));
        }
        #pragma unroll
        for (int i = 0; i < 4; i++) {
            int j = tid + 256 * i;
            int r = j >> 3, cb = (j & 7) << 4;
            cp16(sbase + 16384u + sw128((uint32_t)(r * 128 + cb)),
                 Bp + (long)(col0 + r) * Kp + k0 + (cb >> 1));
        }
    };

    load_stage(su, 0);
    cp_commit();

    for (int t = 0; t < nch; t++) {
        if (t + 1 < nch) {
            load_stage(su + (uint32_t)(((t + 1) & 1) << 15), (t + 1) << 6);
            cp_commit();
            cp_wait1();
        } else {
            cp_wait0();
        }
        __syncthreads();

        const uint32_t sAb = su + (uint32_t)((t & 1) << 15);
        const uint32_t sBb = sAb + 16384u;

        #pragma unroll
        for (int ks = 0; ks < 4; ks++) {
            uint32_t a[4][4], b[4][2];
            #pragma unroll
            for (int mt = 0; mt < 4; mt++) {
                uint32_t off = (uint32_t)((wm * 64 + mt * 16 + (lane & 15)) * 128
                                          + ks * 32 + ((lane >> 4) << 4));
                ldsm4(a[mt], sAb + sw128(off));
            }
            #pragma unroll
            for (int nt = 0; nt < 4; nt++) {
                uint32_t off = (uint32_t)((wn * 32 + nt * 8 + (lane & 7)) * 128
                                          + ks * 32 + (((lane >> 3) & 1) << 4));
                ldsm2(b[nt], sBb + sw128(off));
            }
            #pragma unroll
            for (int mt = 0; mt < 4; mt++)
                #pragma unroll
                for (int nt = 0; nt < 4; nt++)
                    mma16816(acc[mt][nt], a[mt], b[nt]);
        }
        __syncthreads();
    }

    // epilogue
    #pragma unroll
    for (int mt = 0; mt < 4; mt++) {
        int gr0 = row0 + wm * 64 + mt * 16 + (lane >> 2);
        #pragma unroll
        for (int nt = 0; nt < 4; nt++) {
            int gc = col0 + wn * 32 + nt * 8 + ((lane & 3) << 1);
            float b0 = 0.f, b1 = 0.f;
            if (bias) { b0 = bias[gc]; b1 = bias[gc + 1]; }
            #pragma unroll
            for (int h = 0; h < 2; h++) {
                int gr = gr0 + h * 8;
                float v0 = acc[mt][nt][h * 2 + 0] * alpha + b0;
                float v1 = acc[mt][nt][h * 2 + 1] * alpha + b1;
                if (relu2) { v0 = fmaxf(v0, 0.f); v0 *= v0;
                             v1 = fmaxf(v1, 0.f); v1 *= v1; }
                if (resid) {
                    float2 rr = *reinterpret_cast<const float2*>(resid + (long)gr * N + gc);
                    v0 += rr.x; v1 += rr.y;
                }
                if (packout) {
                    __nv_bfloat16* P = reinterpret_cast<__nv_bfloat16*>(C);
                    long base = (long)gr * (3 * N) + gc;
                    __nv_bfloat162 hp, lp;
                    split2(v0, v1, hp, lp);
                    *reinterpret_cast<__nv_bfloat162*>(P + base)         = hp;
                    *reinterpret_cast<__nv_bfloat162*>(P + base + N)     = hp;
                    *reinterpret_cast<__nv_bfloat162*>(P + base + 2 * N) = lp;
                } else {
                    *reinterpret_cast<float2*>(C + (long)gr * N + gc) = make_float2(v0, v1);
                }
            }
        }
    }
}

// ---------------------------------------------------------------------------
// standalone split-pack (weights + q/k): A-mode [hi|hi|lo], B-mode [hi|lo|hi]
// ---------------------------------------------------------------------------
__global__ void __launch_bounds__(256) split_pack(
    const float* __restrict__ src, __nv_bfloat16* __restrict__ dst,
    int K, long total2, int modeB)
{
    long i = (long)blockIdx.x * 256 + threadIdx.x;
    if (i >= total2) return;
    const int K2 = K >> 1;
    long m = i / K2;
    int  k = (int)(i - m * K2) << 1;
    float2 x = *reinterpret_cast<const float2*>(src + m * K + k);
    __nv_bfloat162 hp, lp;
    split2(x.x, x.y, hp, lp);
    long base = m * 3L * K;
    *reinterpret_cast<__nv_bfloat162*>(dst + base + k) = hp;
    if (modeB) {
        *reinterpret_cast<__nv_bfloat162*>(dst + base + K + k)     = lp;
        *reinterpret_cast<__nv_bfloat162*>(dst + base + 2 * K + k) = hp;
    } else {
        *reinterpret_cast<__nv_bfloat162*>(dst + base + K + k)     = hp;
        *reinterpret_cast<__nv_bfloat162*>(dst + base + 2 * K + k) = lp;
    }
}

// ---------------------------------------------------------------------------
// Small SIMT SGEMM for N=64 projections (q, k)
// ---------------------------------------------------------------------------
__global__ void __launch_bounds__(256) sgemm_nt(
    const float* __restrict__ A, const float* __restrict__ Bw, float* __restrict__ C,
    int M, int N, int K, const float* __restrict__ bias)
{
    __shared__ float As[16][64];
    __shared__ float Bs[16][64];
    const int tid = threadIdx.x;
    const int tx = tid & 15, ty = tid >> 4;
    const int row0 = blockIdx.y * 64;
    const int col0 = blockIdx.x * 64;
    const int lr = tid >> 2;
    const int lk = (tid & 3) << 2;
    const float* Apt = A  + (long)(row0 + lr) * K + lk;
    const float* Bpt = Bw + (long)(col0 + lr) * K + lk;
    float acc[4][4];
    #pragma unroll
    for (int i = 0; i < 4; i++)
        #pragma unroll
        for (int j = 0; j < 4; j++) acc[i][j] = 0.f;
    for (int k0 = 0; k0 < K; k0 += 16) {
        float4 a4 = *reinterpret_cast<const float4*>(Apt + k0);
        float4 b4 = *reinterpret_cast<const float4*>(Bpt + k0);
        As[lk+0][lr] = a4.x; As[lk+1][lr] = a4.y; As[lk+2][lr] = a4.z; As[lk+3][lr] = a4.w;
        Bs[lk+0][lr] = b4.x; Bs[lk+1][lr] = b4.y; Bs[lk+2][lr] = b4.z; Bs[lk+3][lr] = b4.w;
        __syncthreads();
        #pragma unroll
        for (int kk = 0; kk < 16; kk++) {
            float4 av = *reinterpret_cast<const float4*>(&As[kk][ty << 2]);
            float4 bv = *reinterpret_cast<const float4*>(&Bs[kk][tx << 2]);
            float a_[4] = {av.x, av.y, av.z, av.w};
            float b_[4] = {bv.x, bv.y, bv.z, bv.w};
            #pragma unroll
            for (int i = 0; i < 4; i++)
                #pragma unroll
                for (int j = 0; j < 4; j++)
                    acc[i][j] += a_[i] * b_[j];
        }
        __syncthreads();
    }
    #pragma unroll
    for (int i = 0; i < 4; i++) {
        int r = row0 + (ty << 2) + i;
        #pragma unroll
        for (int j = 0; j < 4; j++) {
            int c = col0 + (tx << 2) + j;
            float v = acc[i][j];
            if (bias) v += bias[c];
            C[(long)r * N + c] = v;
        }
    }
}

// ---------------------------------------------------------------------------
// rmsnorm: fp32 out + optional packed A-triplet out
// ---------------------------------------------------------------------------
__global__ void __launch_bounds__(256) rmsnorm_k(
    const float* __restrict__ x, const float* __restrict__ w,
    float* __restrict__ out, __nv_bfloat16* __restrict__ pk)
{
    int row = blockIdx.x;
    const float* xr = x + (long)row * Dm;
    int tid = threadIdx.x;
    float ss = 0.f;
    #pragma unroll
    for (int d = tid; d < Dm; d += 256) { float v = xr[d]; ss += v * v; }
    __shared__ float red[256];
    red[tid] = ss; __syncthreads();
    for (int o = 128; o; o >>= 1) {
        if (tid < o) red[tid] += red[tid + o];
        __syncthreads();
    }
    float scale = 1.f / (sqrtf(red[0] * (1.f / Dm)) + 1e-8f);
    #pragma unroll
    for (int d = tid; d < Dm; d += 256) {
        float v = w[d] * xr[d] * scale;
        out[(long)row * Dm + d] = v;
        if (pk) {
            __nv_bfloat16 h = __float2bfloat16_rn(v);
            __nv_bfloat16 l = __float2bfloat16_rn(v - __bfloat162float(h));
            long base = (long)row * (3 * Dm) + d;
            pk[base] = h; pk[base + Dm] = h; pk[base + 2 * Dm] = l;
        }
    }
}

// ---------------------------------------------------------------------------
// token-shift mixes -> two packed A-operands directly (no fp32 intermediate)
// ---------------------------------------------------------------------------
__global__ void __launch_bounds__(256) mix2pack_k(
    const float* __restrict__ xn, const float* __restrict__ m1,
    const float* __restrict__ m2,
    __nv_bfloat16* __restrict__ p1, __nv_bfloat16* __restrict__ p2)
{
    long pi2 = (long)blockIdx.x * 256 + threadIdx.x;   // pair index
    long i = pi2 << 1;                                  // element index
    int d = (int)(i & (Dm - 1));
    int s = (int)((i >> 10) & (Sm - 1));
    long prev = s ? (i - Dm) : i;
    float2 cur = *reinterpret_cast<const float2*>(xn + i);
    float2 prv = *reinterpret_cast<const float2*>(xn + prev);
    float a0 = m1[d], a1 = m1[d + 1];
    float b0 = m2[d], b1 = m2[d + 1];
    float o10 = cur.x * a0 + prv.x * (1.f - a0);
    float o11 = cur.y * a1 + prv.y * (1.f - a1);
    float o20 = cur.x * b0 + prv.x * (1.f - b0);
    float o21 = cur.y * b1 + prv.y * (1.f - b1);
    long row = i >> 10;
    long base = row * (3 * Dm) + d;
    __nv_bfloat162 hp, lp;
    split2(o10, o11, hp, lp);
    *reinterpret_cast<__nv_bfloat162*>(p1 + base)          = hp;
    *reinterpret_cast<__nv_bfloat162*>(p1 + base + Dm)     = hp;
    *reinterpret_cast<__nv_bfloat162*>(p1 + base + 2 * Dm) = lp;
    split2(o20, o21, hp, lp);
    *reinterpret_cast<__nv_bfloat162*>(p2 + base)          = hp;
    *reinterpret_cast<__nv_bfloat162*>(p2 + base + Dm)     = hp;
    *reinterpret_cast<__nv_bfloat162*>(p2 + base + 2 * Dm) = lp;
}

// ---------------------------------------------------------------------------
// top-32 (owner-rescan) + softmax + V-gather -> packed att
// ---------------------------------------------------------------------------
__global__ void __launch_bounds__(128) topk_attn_k(
    const float* __restrict__ Sc, const float* __restrict__ Vsa,
    __nv_bfloat16* __restrict__ OutP)
{
    int q = blockIdx.x;
    int b = q >> 12;
    const float* srow = Sc + (long)q * Sm;

    __shared__ float topv[KTOP];
    __shared__ int   topi[KTOP];
    __shared__ float wmv[4];
    __shared__ int   wiv[4];
    __shared__ int   sel;
    __shared__ float p[KTOP];

    const int tid  = threadIdx.x;
    const int lane = tid & 31;
    const int wrp  = tid >> 5;

    // slice in registers: global index = tid + 128*slot
    float sv[32];
    #pragma unroll
    for (int i = 0; i < 32; i++) sv[i] = srow[tid + (i << 7)];

    float best = -INFINITY; int bloc = 0;
    #pragma unroll
    for (int i = 0; i < 32; i++)
        if (sv[i] > best) { best = sv[i]; bloc = i; }

    for (int it = 0; it < KTOP; it++) {
        float cb = best;
        int   ci = tid + (bloc << 7);
        #pragma unroll
        for (int o = 16; o; o >>= 1) {
            float ov = __shfl_down_sync(0xffffffffu, cb, o);
            int   oi = __shfl_down_sync(0xffffffffu, ci, o);
            if (ov > cb || (ov == cb && oi < ci)) { cb = ov; ci = oi; }
        }
        if (lane == 0) { wmv[wrp] = cb; wiv[wrp] = ci; }
        __syncthreads();
        if (tid == 0) {
            float bb = wmv[0]; int bj = wiv[0];
            #pragma unroll
            for (int w2 = 1; w2 < 4; w2++)
                if (wmv[w2] > bb || (wmv[w2] == bb && wiv[w2] < bj)) { bb = wmv[w2]; bj = wiv[w2]; }
            topv[it] = bb; topi[it] = bj; sel = bj;
        }
        __syncthreads();
        int bj = sel;
        if ((bj & 127) == tid) {
            sv[bj >> 7] = -INFINITY;
            best = -INFINITY; bloc = 0;
            #pragma unroll
            for (int i = 0; i < 32; i++)
                if (sv[i] > best) { best = sv[i]; bloc = i; }
        }
        __syncthreads();
    }

    if (tid == 0) {
        float mx = topv[0], Z = 0.f;
        #pragma unroll
        for (int i2 = 0; i2 < KTOP; i2++) { float e = expf(topv[i2] - mx); p[i2] = e; Z += e; }
        float iz = 1.f / Z;
        #pragma unroll
        for (int i2 = 0; i2 < KTOP; i2++) p[i2] *= iz;
    }
    __syncthreads();

    const float* Vb = Vsa + (long)b * Sm * Dm;
    for (int d = tid; d < Dm; d += 128) {
        float acc = 0.f;
        #pragma unroll
        for (int i2 = 0; i2 < KTOP; i2++)
            acc += p[i2] * Vb[(long)topi[i2] * Dm + d];
        __nv_bfloat16 h = __float2bfloat16_rn(acc);
        __nv_bfloat16 l = __float2bfloat16_rn(acc - __bfloat162float(h));
        long base = (long)q * (3 * Dm) + d;
        OutP[base] = h; OutP[base + Dm] = h; OutP[base + 2 * Dm] = l;
    }
}

// ---------------------------------------------------------------------------
// gates: rkv -> packed; final -> out
// ---------------------------------------------------------------------------
__global__ void __launch_bounds__(256) rkvpack_k(
    const float* __restrict__ r, const float* __restrict__ ao,
    const float* __restrict__ v, __nv_bfloat16* __restrict__ p1)
{
    long pi2 = (long)blockIdx.x * 256 + threadIdx.x;
    long i = pi2 << 1;
    float2 rr = *reinterpret_cast<const float2*>(r + i);
    float2 aa = *reinterpret_cast<const float2*>(ao + i);
    float2 vv = *reinterpret_cast<const float2*>(v + i);
    float o0 = (1.f / (1.f + expf(-rr.x))) * (aa.x + vv.x);
    float o1 = (1.f / (1.f + expf(-rr.y))) * (aa.y + vv.y);
    long row = i >> 10;
    int  d = (int)(i & (Dm - 1));
    long base = row * (3 * Dm) + d;
    __nv_bfloat162 hp, lp;
    split2(o0, o1, hp, lp);
    *reinterpret_cast<__nv_bfloat162*>(p1 + base)          = hp;
    *reinterpret_cast<__nv_bfloat162*>(p1 + base + Dm)     = hp;
    *reinterpret_cast<__nv_bfloat162*>(p1 + base + 2 * Dm) = lp;
}

__global__ void __launch_bounds__(256) final_k(
    const float* __restrict__ x1, const float* __restrict__ r2,
    const float* __restrict__ kv, float* __restrict__ o)
{
    long i = (long)blockIdx.x * 256 + threadIdx.x;
    float sig = 1.f / (1.f + expf(-r2[i]));
    o[i] = x1[i] + sig * kv[i];
}

// ---------------------------------------------------------------------------
// launcher
// ---------------------------------------------------------------------------
extern "C" void kernel_launch(void* const* d_in, const int* in_sizes, int n_in,
                              void* d_out, int out_size)
{
    const float* x           = (const float*)d_in[0];
    const float* norm1_w     = (const float*)d_in[1];
    const float* tm_mix_v    = (const float*)d_in[3];
    const float* tm_mix_r    = (const float*)d_in[4];
    // d_in[2]=tm_mix_k, d_in[5]=tm_key_w: dead in reference
    const float* tm_value_w  = (const float*)d_in[6];
    const float* tm_recept_w = (const float*)d_in[7];
    const float* tm_out_w    = (const float*)d_in[8];
    const float* sa_q_w      = (const float*)d_in[9];
    const float* sa_q_b      = (const float*)d_in[10];
    const float* sa_k_w      = (const float*)d_in[11];
    const float* sa_k_b      = (const float*)d_in[12];
    const float* sa_v_w      = (const float*)d_in[13];
    const float* sa_v_b      = (const float*)d_in[14];
    const float* sa_o_w      = (const float*)d_in[15];
    const float* sa_o_b      = (const float*)d_in[16];
    const float* norm2_w     = (const float*)d_in[17];
    const float* cm_mix_k    = (const float*)d_in[18];
    const float* cm_mix_r    = (const float*)d_in[19];
    const float* cm_key_w    = (const float*)d_in[20];
    const float* cm_recept_w = (const float*)d_in[21];
    const float* cm_value_w  = (const float*)d_in[22];
    float* out = (float*)d_out;

    float *xn, *v, *r, *q, *kk, *vsa, *ao, *x1, *big;
    __nv_bfloat16 *pA1, *pA2, *pXN, *pBIG, *pQ, *pK, *wpk;
    cudaGetSymbolAddress((void**)&xn,   g_xn);
    cudaGetSymbolAddress((void**)&v,    g_v);
    cudaGetSymbolAddress((void**)&r,    g_r);
    cudaGetSymbolAddress((void**)&q,    g_q);
    cudaGetSymbolAddress((void**)&kk,   g_k);
    cudaGetSymbolAddress((void**)&vsa,  g_vsa);
    cudaGetSymbolAddress((void**)&ao,   g_ao);
    cudaGetSymbolAddress((void**)&x1,   g_x1);
    cudaGetSymbolAddress((void**)&big,  g_big);
    cudaGetSymbolAddress((void**)&pA1,  g_pA1);
    cudaGetSymbolAddress((void**)&pA2,  g_pA2);
    cudaGetSymbolAddress((void**)&pXN,  g_pXN);
    cudaGetSymbolAddress((void**)&pBIG, g_pBIG);
    cudaGetSymbolAddress((void**)&pQ,   g_pQ);
    cudaGetSymbolAddress((void**)&pK,   g_pK);
    cudaGetSymbolAddress((void**)&wpk,  g_wpk);

    cudaFuncSetAttribute(mma_gemm, cudaFuncAttributeMaxDynamicSharedMemorySize, MG_SMEM);

    const dim3 gD (Dm / 128,  NT / 128);
    const dim3 gDI(DIm / 128, NT / 128);
    const dim3 gS (Sm / 128,  Sm / 128, Bb);
    const dim3 gA (Am / 64,   NT / 64);
    const int  pairBlocks = NT * Dm / 512;   // pair-granular elementwise
    const int  Kp1 = 3 * Dm;                 // 3072
    const int  Kp4 = 3 * DIm;                // 12288
    const int  KpS = 3 * Am;                 // 192

    auto wpack = [&](const float* w, int K, long rows) {
        long t = rows * K / 2;
        split_pack<<<(unsigned)((t + 255) / 256), 256>>>(w, wpk, K, t, 1);
    };

    // ---- time mix ----
    rmsnorm_k<<<NT, 256>>>(x, norm1_w, xn, pXN);
    mix2pack_k<<<pairBlocks, 256>>>(xn, tm_mix_v, tm_mix_r, pA1, pA2);

    wpack(tm_value_w, Dm, Dm);
    mma_gemm<<<gD, 256, MG_SMEM>>>(pA1, wpk, v, Dm, Kp1, 0, 0, 0, nullptr, nullptr, 1.f, 0, 0);

    wpack(tm_recept_w, Dm, Dm);
    mma_gemm<<<gD, 256, MG_SMEM>>>(pA2, wpk, r, Dm, Kp1, 0, 0, 0, nullptr, nullptr, 1.f, 0, 0);

    sgemm_nt<<<gA, 256>>>(xn, sa_q_w, q,  NT, Am, Dm, sa_q_b);
    sgemm_nt<<<gA, 256>>>(xn, sa_k_w, kk, NT, Am, Dm, sa_k_b);

    wpack(sa_v_w, Dm, Dm);
    mma_gemm<<<gD, 256, MG_SMEM>>>(pXN, wpk, vsa, Dm, Kp1, 0, 0, 0, sa_v_b, nullptr, 1.f, 0, 0);

    {   // q/k packs (small)
        long tq = (long)NT * Am / 2;
        split_pack<<<(unsigned)((tq + 255) / 256), 256>>>(q,  pQ, Am, tq, 0);
        split_pack<<<(unsigned)((tq + 255) / 256), 256>>>(kk, pK, Am, tq, 1);
    }
    mma_gemm<<<gS, 256, MG_SMEM>>>(pQ, pK, big, Sm, KpS,
                                   (long)Sm * KpS, (long)Sm * KpS, (long)Sm * Sm,
                                   nullptr, nullptr, 0.125f, 0, 0);

    topk_attn_k<<<NT, 128>>>(big, vsa, pA1);

    wpack(sa_o_w, Dm, Dm);
    mma_gemm<<<gD, 256, MG_SMEM>>>(pA1, wpk, ao, Dm, Kp1, 0, 0, 0, sa_o_b, nullptr, 1.f, 0, 0);

    rkvpack_k<<<pairBlocks, 256>>>(r, ao, v, pA2);

    wpack(tm_out_w, Dm, Dm);
    mma_gemm<<<gD, 256, MG_SMEM>>>(pA2, wpk, x1, Dm, Kp1, 0, 0, 0, nullptr, x, 1.f, 0, 0);

    // ---- channel mix ----
    rmsnorm_k<<<NT, 256>>>(x1, norm2_w, xn, nullptr);
    mix2pack_k<<<pairBlocks, 256>>>(xn, cm_mix_k, cm_mix_r, pA1, pA2);

    wpack(cm_key_w, Dm, DIm);
    mma_gemm<<<gDI, 256, MG_SMEM>>>(pA1, wpk, (float*)pBIG, DIm, Kp1,
                                    0, 0, 0, nullptr, nullptr, 1.f, 1, 1);  // relu^2 -> packed

    wpack(cm_recept_w, Dm, Dm);
    mma_gemm<<<gD, 256, MG_SMEM>>>(pA2, wpk, r, Dm, Kp1, 0, 0, 0, nullptr, nullptr, 1.f, 0, 0);

    wpack(cm_value_w, DIm, Dm);
    mma_gemm<<<gD, 256, MG_SMEM>>>(pBIG, wpk, v, Dm, Kp4, 0, 0, 0, nullptr, nullptr, 1.f, 0, 0);

    final_k<<<2 * pairBlocks, 256>>>(x1, r, v, out);
}

// round 9
// speedup vs baseline: 3.3533x; 1.1078x over previous
#include <cuda_runtime.h>
#include <cuda_bf16.h>
#include <math.h>
#include <stdint.h>

// Problem constants
#define Dm   1024
#define Sm   4096
#define Bb   2
#define DIm  4096
#define NT   (Bb*Sm)       // 8192 token rows
#define KTOP 32
#define Am   64

// ---------------------------------------------------------------------------
// Scratch (static device globals). Packed operands are PLANE layout:
// [hi plane (rows*K)][lo plane (rows*K)]
// ---------------------------------------------------------------------------
__device__ float g_xn [NT*Dm];
__device__ float g_v  [NT*Dm];
__device__ float g_r  [NT*Dm];
__device__ float g_q  [NT*Am];
__device__ float g_k  [NT*Am];
__device__ float g_vsa[NT*Dm];
__device__ float g_ao [NT*Dm];
__device__ float g_x1 [NT*Dm];
__device__ float g_big[(size_t)NT*Sm];                               // scores
__device__ __align__(16) __nv_bfloat16 g_pA1 [(size_t)2*NT*Dm];
__device__ __align__(16) __nv_bfloat16 g_pA2 [(size_t)2*NT*Dm];
__device__ __align__(16) __nv_bfloat16 g_pXN [(size_t)2*NT*Dm];
__device__ __align__(16) __nv_bfloat16 g_pBIG[(size_t)2*NT*DIm];
__device__ __align__(16) __nv_bfloat16 g_pQ  [(size_t)2*NT*Am];
__device__ __align__(16) __nv_bfloat16 g_pK  [(size_t)2*NT*Am];
__device__ __align__(16) __nv_bfloat16 g_wpk [(size_t)2*DIm*Dm];

// ---------------------------------------------------------------------------
// PTX helpers (legal at compute_103)
// ---------------------------------------------------------------------------
__device__ __forceinline__ uint32_t smem_u32(const void* p) {
    uint32_t a;
    asm("{ .reg .u64 t; cvta.to.shared.u64 t, %1; cvt.u32.u64 %0, t; }" : "=r"(a) : "l"(p));
    return a;
}
__device__ __forceinline__ uint32_t sw128(uint32_t o) { return o ^ ((o >> 3) & 0x70); }

__device__ __forceinline__ void cp16(uint32_t s, const void* g) {
    asm volatile("cp.async.cg.shared.global [%0], [%1], 16;" :: "r"(s), "l"(g));
}
__device__ __forceinline__ void cp_commit() { asm volatile("cp.async.commit_group;" ::: "memory"); }
__device__ __forceinline__ void cp_wait0()  { asm volatile("cp.async.wait_group 0;" ::: "memory"); }
__device__ __forceinline__ void cp_wait1()  { asm volatile("cp.async.wait_group 1;" ::: "memory"); }

__device__ __forceinline__ void ldsm4(uint32_t* r, uint32_t a) {
    asm volatile("ldmatrix.sync.aligned.m8n8.x4.shared.b16 {%0,%1,%2,%3}, [%4];"
                 : "=r"(r[0]), "=r"(r[1]), "=r"(r[2]), "=r"(r[3]) : "r"(a));
}
__device__ __forceinline__ void mma16816(float* c, const uint32_t* a, uint32_t b0, uint32_t b1) {
    asm volatile(
        "mma.sync.aligned.m16n8k16.row.col.f32.bf16.bf16.f32 "
        "{%0,%1,%2,%3}, {%4,%5,%6,%7}, {%8,%9}, {%0,%1,%2,%3};"
        : "+f"(c[0]), "+f"(c[1]), "+f"(c[2]), "+f"(c[3])
        : "r"(a[0]), "r"(a[1]), "r"(a[2]), "r"(a[3]), "r"(b0), "r"(b1));
}

__device__ __forceinline__ void split2(float v0, float v1,
                                       __nv_bfloat162& hp, __nv_bfloat162& lp) {
    __nv_bfloat16 h0 = __float2bfloat16_rn(v0);
    __nv_bfloat16 h1 = __float2bfloat16_rn(v1);
    __nv_bfloat16 l0 = __float2bfloat16_rn(v0 - __bfloat162float(h0));
    __nv_bfloat16 l1 = __float2bfloat16_rn(v1 - __bfloat162float(h1));
    hp.x = h0; hp.y = h1; lp.x = l0; lp.y = l1;
}

// ---------------------------------------------------------------------------
// mma.sync NT GEMM on hi/lo planes: C = alpha*(Ahi·Bhi + Alo·Bhi + Ahi·Blo)
// CTA tile 128x256, warp tile 64x64 (8 warps 2x4), BK=64, 2-stage cp.async.
// Requires M%128==0, N%256==0, K%64==0.
// packout: write hi/lo planes (lo at +pOfs) instead of fp32.
// ---------------------------------------------------------------------------
#define ST_A_LO 16384u
#define ST_BHI  32768u
#define ST_BLO  65536u
#define ST_SZ   98304u
#define MG_SMEM 196608

__global__ void __launch_bounds__(256, 1) mma_gemm(
    const __nv_bfloat16* __restrict__ Ap, long aLo,
    const __nv_bfloat16* __restrict__ Bp, long bLo,
    float* __restrict__ C, int N, int K,
    long sA, long sB, long sC,
    const float* __restrict__ bias, const float* __restrict__ resid,
    float alpha, int relu2, int packout, long pOfs)
{
    extern __shared__ char smem[];
    const __nv_bfloat16* Ahi = Ap + (long)blockIdx.z * sA;
    const __nv_bfloat16* Alo = Ap + aLo + (long)blockIdx.z * sA;
    const __nv_bfloat16* Bhi = Bp + (long)blockIdx.z * sB;
    const __nv_bfloat16* Blo = Bp + bLo + (long)blockIdx.z * sB;
    C += (long)blockIdx.z * sC;
    if (resid) resid += (long)blockIdx.z * sC;

    const int tid  = threadIdx.x;
    const int lane = tid & 31;
    const int wid  = tid >> 5;
    const int wm   = wid >> 2;           // 0..1
    const int wn   = wid & 3;            // 0..3
    const int row0 = blockIdx.y * 128;
    const int col0 = blockIdx.x * 256;
    const uint32_t su = smem_u32(smem);

    float acc[4][8][4];
    #pragma unroll
    for (int mt = 0; mt < 4; mt++)
        #pragma unroll
        for (int nt = 0; nt < 8; nt++)
            #pragma unroll
            for (int i = 0; i < 4; i++) acc[mt][nt][i] = 0.f;

    const int nch = K >> 6;

    auto load_stage = [&](uint32_t sbase, int k0) {
        #pragma unroll
        for (int i = 0; i < 4; i++) {
            int j = tid + 256 * i; int r = j >> 3, cb = (j & 7) << 4;
            cp16(sbase + sw128((uint32_t)(r * 128 + cb)),
                 Ahi + (long)(row0 + r) * K + k0 + (cb >> 1));
        }
        #pragma unroll
        for (int i = 0; i < 4; i++) {
            int j = tid + 256 * i; int r = j >> 3, cb = (j & 7) << 4;
            cp16(sbase + ST_A_LO + sw128((uint32_t)(r * 128 + cb)),
                 Alo + (long)(row0 + r) * K + k0 + (cb >> 1));
        }
        #pragma unroll
        for (int i = 0; i < 8; i++) {
            int j = tid + 256 * i; int r = j >> 3, cb = (j & 7) << 4;
            cp16(sbase + ST_BHI + sw128((uint32_t)(r * 128 + cb)),
                 Bhi + (long)(col0 + r) * K + k0 + (cb >> 1));
        }
        #pragma unroll
        for (int i = 0; i < 8; i++) {
            int j = tid + 256 * i; int r = j >> 3, cb = (j & 7) << 4;
            cp16(sbase + ST_BLO + sw128((uint32_t)(r * 128 + cb)),
                 Blo + (long)(col0 + r) * K + k0 + (cb >> 1));
        }
    };

    load_stage(su, 0);
    cp_commit();

    for (int t = 0; t < nch; t++) {
        if (t + 1 < nch) {
            load_stage(su + (((t + 1) & 1) ? ST_SZ : 0u), (t + 1) << 6);
            cp_commit();
            cp_wait1();
        } else {
            cp_wait0();
        }
        __syncthreads();

        const uint32_t sb  = su + ((t & 1) ? ST_SZ : 0u);
        const uint32_t sAh = sb;
        const uint32_t sAl = sb + ST_A_LO;
        const uint32_t sBh = sb + ST_BHI;
        const uint32_t sBl = sb + ST_BLO;

        #pragma unroll
        for (int ks = 0; ks < 4; ks++) {
            uint32_t ahi[4][4], alo[4][4];
            #pragma unroll
            for (int mt = 0; mt < 4; mt++) {
                uint32_t off = (uint32_t)((wm * 64 + mt * 16 + (lane & 15)) * 128
                                          + ks * 32 + ((lane >> 4) << 4));
                ldsm4(ahi[mt], sAh + sw128(off));
                ldsm4(alo[mt], sAl + sw128(off));
            }
            #pragma unroll
            for (int ntp = 0; ntp < 4; ntp++) {
                int g = lane >> 3;
                uint32_t off = (uint32_t)((wn * 64 + ntp * 16 + (lane & 7) + (g >> 1) * 8) * 128
                                          + ks * 32 + (g & 1) * 16);
                uint32_t bh[4], bl[4];
                ldsm4(bh, sBh + sw128(off));
                ldsm4(bl, sBl + sw128(off));
                #pragma unroll
                for (int s = 0; s < 2; s++) {
                    int nt = ntp * 2 + s;
                    uint32_t b0h = bh[2 * s], b1h = bh[2 * s + 1];
                    uint32_t b0l = bl[2 * s], b1l = bl[2 * s + 1];
                    #pragma unroll
                    for (int mt = 0; mt < 4; mt++) {
                        mma16816(acc[mt][nt], ahi[mt], b0h, b1h);
                        mma16816(acc[mt][nt], alo[mt], b0h, b1h);
                        mma16816(acc[mt][nt], ahi[mt], b0l, b1l);
                    }
                }
            }
        }
        __syncthreads();
    }

    // epilogue
    #pragma unroll
    for (int mt = 0; mt < 4; mt++) {
        int gr0 = row0 + wm * 64 + mt * 16 + (lane >> 2);
        #pragma unroll
        for (int nt = 0; nt < 8; nt++) {
            int gc = col0 + wn * 64 + nt * 8 + ((lane & 3) << 1);
            float b0 = 0.f, b1 = 0.f;
            if (bias) { b0 = bias[gc]; b1 = bias[gc + 1]; }
            #pragma unroll
            for (int h = 0; h < 2; h++) {
                int gr = gr0 + h * 8;
                float v0 = acc[mt][nt][h * 2 + 0] * alpha + b0;
                float v1 = acc[mt][nt][h * 2 + 1] * alpha + b1;
                if (relu2) { v0 = fmaxf(v0, 0.f); v0 *= v0;
                             v1 = fmaxf(v1, 0.f); v1 *= v1; }
                if (resid) {
                    float2 rr = *reinterpret_cast<const float2*>(resid + (long)gr * N + gc);
                    v0 += rr.x; v1 += rr.y;
                }
                if (packout) {
                    __nv_bfloat16* P = reinterpret_cast<__nv_bfloat16*>(C);
                    long base = (long)gr * N + gc;
                    __nv_bfloat162 hp, lp;
                    split2(v0, v1, hp, lp);
                    *reinterpret_cast<__nv_bfloat162*>(P + base)        = hp;
                    *reinterpret_cast<__nv_bfloat162*>(P + base + pOfs) = lp;
                } else {
                    *reinterpret_cast<float2*>(C + (long)gr * N + gc) = make_float2(v0, v1);
                }
            }
        }
    }
}

// ---------------------------------------------------------------------------
// split-pack to hi/lo planes
// ---------------------------------------------------------------------------
__global__ void __launch_bounds__(256) split_pack_pl(
    const float* __restrict__ src, __nv_bfloat16* __restrict__ dst,
    long total2, long planeOfs)
{
    long i = (long)blockIdx.x * 256 + threadIdx.x;
    if (i >= total2) return;
    long e = i << 1;
    float2 x = *reinterpret_cast<const float2*>(src + e);
    __nv_bfloat162 hp, lp;
    split2(x.x, x.y, hp, lp);
    *reinterpret_cast<__nv_bfloat162*>(dst + e)            = hp;
    *reinterpret_cast<__nv_bfloat162*>(dst + planeOfs + e) = lp;
}

// ---------------------------------------------------------------------------
// Small SIMT SGEMM for N=64 projections (q, k)
// ---------------------------------------------------------------------------
__global__ void __launch_bounds__(256) sgemm_nt(
    const float* __restrict__ A, const float* __restrict__ Bw, float* __restrict__ C,
    int M, int N, int K, const float* __restrict__ bias)
{
    __shared__ float As[16][64];
    __shared__ float Bs[16][64];
    const int tid = threadIdx.x;
    const int tx = tid & 15, ty = tid >> 4;
    const int row0 = blockIdx.y * 64;
    const int col0 = blockIdx.x * 64;
    const int lr = tid >> 2;
    const int lk = (tid & 3) << 2;
    const float* Apt = A  + (long)(row0 + lr) * K + lk;
    const float* Bpt = Bw + (long)(col0 + lr) * K + lk;
    float acc[4][4];
    #pragma unroll
    for (int i = 0; i < 4; i++)
        #pragma unroll
        for (int j = 0; j < 4; j++) acc[i][j] = 0.f;
    for (int k0 = 0; k0 < K; k0 += 16) {
        float4 a4 = *reinterpret_cast<const float4*>(Apt + k0);
        float4 b4 = *reinterpret_cast<const float4*>(Bpt + k0);
        As[lk+0][lr] = a4.x; As[lk+1][lr] = a4.y; As[lk+2][lr] = a4.z; As[lk+3][lr] = a4.w;
        Bs[lk+0][lr] = b4.x; Bs[lk+1][lr] = b4.y; Bs[lk+2][lr] = b4.z; Bs[lk+3][lr] = b4.w;
        __syncthreads();
        #pragma unroll
        for (int kk = 0; kk < 16; kk++) {
            float4 av = *reinterpret_cast<const float4*>(&As[kk][ty << 2]);
            float4 bv = *reinterpret_cast<const float4*>(&Bs[kk][tx << 2]);
            float a_[4] = {av.x, av.y, av.z, av.w};
            float b_[4] = {bv.x, bv.y, bv.z, bv.w};
            #pragma unroll
            for (int i = 0; i < 4; i++)
                #pragma unroll
                for (int j = 0; j < 4; j++)
                    acc[i][j] += a_[i] * b_[j];
        }
        __syncthreads();
    }
    #pragma unroll
    for (int i = 0; i < 4; i++) {
        int r = row0 + (ty << 2) + i;
        #pragma unroll
        for (int j = 0; j < 4; j++) {
            int c = col0 + (tx << 2) + j;
            float v = acc[i][j];
            if (bias) v += bias[c];
            C[(long)r * N + c] = v;
        }
    }
}

// ---------------------------------------------------------------------------
// rmsnorm: fp32 out + optional hi/lo plane out
// ---------------------------------------------------------------------------
__global__ void __launch_bounds__(256) rmsnorm_k(
    const float* __restrict__ x, const float* __restrict__ w,
    float* __restrict__ out, __nv_bfloat16* __restrict__ pk, long planeOfs)
{
    int row = blockIdx.x;
    const float* xr = x + (long)row * Dm;
    int tid = threadIdx.x;
    float ss = 0.f;
    #pragma unroll
    for (int d = tid; d < Dm; d += 256) { float v = xr[d]; ss += v * v; }
    __shared__ float red[256];
    red[tid] = ss; __syncthreads();
    for (int o = 128; o; o >>= 1) {
        if (tid < o) red[tid] += red[tid + o];
        __syncthreads();
    }
    float scale = 1.f / (sqrtf(red[0] * (1.f / Dm)) + 1e-8f);
    #pragma unroll
    for (int d = tid; d < Dm; d += 256) {
        float v = w[d] * xr[d] * scale;
        long e = (long)row * Dm + d;
        out[e] = v;
        if (pk) {
            __nv_bfloat16 h = __float2bfloat16_rn(v);
            __nv_bfloat16 l = __float2bfloat16_rn(v - __bfloat162float(h));
            pk[e] = h; pk[e + planeOfs] = l;
        }
    }
}

// ---------------------------------------------------------------------------
// token-shift mixes -> two hi/lo-plane packed A operands
// ---------------------------------------------------------------------------
__global__ void __launch_bounds__(256) mix2pack_k(
    const float* __restrict__ xn, const float* __restrict__ m1,
    const float* __restrict__ m2,
    __nv_bfloat16* __restrict__ p1, __nv_bfloat16* __restrict__ p2, long planeOfs)
{
    long pi2 = (long)blockIdx.x * 256 + threadIdx.x;
    long i = pi2 << 1;
    int d = (int)(i & (Dm - 1));
    int s = (int)((i >> 10) & (Sm - 1));
    long prev = s ? (i - Dm) : i;
    float2 cur = *reinterpret_cast<const float2*>(xn + i);
    float2 prv = *reinterpret_cast<const float2*>(xn + prev);
    float a0 = m1[d], a1 = m1[d + 1];
    float b0 = m2[d], b1 = m2[d + 1];
    float o10 = cur.x * a0 + prv.x * (1.f - a0);
    float o11 = cur.y * a1 + prv.y * (1.f - a1);
    float o20 = cur.x * b0 + prv.x * (1.f - b0);
    float o21 = cur.y * b1 + prv.y * (1.f - b1);
    __nv_bfloat162 hp, lp;
    split2(o10, o11, hp, lp);
    *reinterpret_cast<__nv_bfloat162*>(p1 + i)            = hp;
    *reinterpret_cast<__nv_bfloat162*>(p1 + planeOfs + i) = lp;
    split2(o20, o21, hp, lp);
    *reinterpret_cast<__nv_bfloat162*>(p2 + i)            = hp;
    *reinterpret_cast<__nv_bfloat162*>(p2 + planeOfs + i) = lp;
}

// ---------------------------------------------------------------------------
// top-32 (owner-rescan) + softmax + V-gather -> hi/lo planes
// ---------------------------------------------------------------------------
__global__ void __launch_bounds__(128) topk_attn_k(
    const float* __restrict__ Sc, const float* __restrict__ Vsa,
    __nv_bfloat16* __restrict__ OutP, long planeOfs)
{
    int q = blockIdx.x;
    int b = q >> 12;
    const float* srow = Sc + (long)q * Sm;

    __shared__ float topv[KTOP];
    __shared__ int   topi[KTOP];
    __shared__ float wmv[4];
    __shared__ int   wiv[4];
    __shared__ int   sel;
    __shared__ float p[KTOP];

    const int tid  = threadIdx.x;
    const int lane = tid & 31;
    const int wrp  = tid >> 5;

    float sv[32];
    #pragma unroll
    for (int i = 0; i < 32; i++) sv[i] = srow[tid + (i << 7)];

    float best = -INFINITY; int bloc = 0;
    #pragma unroll
    for (int i = 0; i < 32; i++)
        if (sv[i] > best) { best = sv[i]; bloc = i; }

    for (int it = 0; it < KTOP; it++) {
        float cb = best;
        int   ci = tid + (bloc << 7);
        #pragma unroll
        for (int o = 16; o; o >>= 1) {
            float ov = __shfl_down_sync(0xffffffffu, cb, o);
            int   oi = __shfl_down_sync(0xffffffffu, ci, o);
            if (ov > cb || (ov == cb && oi < ci)) { cb = ov; ci = oi; }
        }
        if (lane == 0) { wmv[wrp] = cb; wiv[wrp] = ci; }
        __syncthreads();
        if (tid == 0) {
            float bb = wmv[0]; int bj = wiv[0];
            #pragma unroll
            for (int w2 = 1; w2 < 4; w2++)
                if (wmv[w2] > bb || (wmv[w2] == bb && wiv[w2] < bj)) { bb = wmv[w2]; bj = wiv[w2]; }
            topv[it] = bb; topi[it] = bj; sel = bj;
        }
        __syncthreads();
        int bj = sel;
        if ((bj & 127) == tid) {
            sv[bj >> 7] = -INFINITY;
            best = -INFINITY; bloc = 0;
            #pragma unroll
            for (int i = 0; i < 32; i++)
                if (sv[i] > best) { best = sv[i]; bloc = i; }
        }
        __syncthreads();
    }

    if (tid == 0) {
        float mx = topv[0], Z = 0.f;
        #pragma unroll
        for (int i2 = 0; i2 < KTOP; i2++) { float e = expf(topv[i2] - mx); p[i2] = e; Z += e; }
        float iz = 1.f / Z;
        #pragma unroll
        for (int i2 = 0; i2 < KTOP; i2++) p[i2] *= iz;
    }
    __syncthreads();

    const float* Vb = Vsa + (long)b * Sm * Dm;
    for (int d = tid; d < Dm; d += 128) {
        float acc = 0.f;
        #pragma unroll
        for (int i2 = 0; i2 < KTOP; i2++)
            acc += p[i2] * Vb[(long)topi[i2] * Dm + d];
        __nv_bfloat16 h = __float2bfloat16_rn(acc);
        __nv_bfloat16 l = __float2bfloat16_rn(acc - __bfloat162float(h));
        long e = (long)q * Dm + d;
        OutP[e] = h; OutP[e + planeOfs] = l;
    }
}

// ---------------------------------------------------------------------------
// gates
// ---------------------------------------------------------------------------
__global__ void __launch_bounds__(256) rkvpack_k(
    const float* __restrict__ r, const float* __restrict__ ao,
    const float* __restrict__ v, __nv_bfloat16* __restrict__ p1, long planeOfs)
{
    long pi2 = (long)blockIdx.x * 256 + threadIdx.x;
    long i = pi2 << 1;
    float2 rr = *reinterpret_cast<const float2*>(r + i);
    float2 aa = *reinterpret_cast<const float2*>(ao + i);
    float2 vv = *reinterpret_cast<const float2*>(v + i);
    float o0 = (1.f / (1.f + expf(-rr.x))) * (aa.x + vv.x);
    float o1 = (1.f / (1.f + expf(-rr.y))) * (aa.y + vv.y);
    __nv_bfloat162 hp, lp;
    split2(o0, o1, hp, lp);
    *reinterpret_cast<__nv_bfloat162*>(p1 + i)            = hp;
    *reinterpret_cast<__nv_bfloat162*>(p1 + planeOfs + i) = lp;
}

__global__ void __launch_bounds__(256) final_k(
    const float* __restrict__ x1, const float* __restrict__ r2,
    const float* __restrict__ kv, float* __restrict__ o)
{
    long i = (long)blockIdx.x * 256 + threadIdx.x;
    float sig = 1.f / (1.f + expf(-r2[i]));
    o[i] = x1[i] + sig * kv[i];
}

// ---------------------------------------------------------------------------
// launcher
// ---------------------------------------------------------------------------
extern "C" void kernel_launch(void* const* d_in, const int* in_sizes, int n_in,
                              void* d_out, int out_size)
{
    const float* x           = (const float*)d_in[0];
    const float* norm1_w     = (const float*)d_in[1];
    const float* tm_mix_v    = (const float*)d_in[3];
    const float* tm_mix_r    = (const float*)d_in[4];
    // d_in[2]=tm_mix_k, d_in[5]=tm_key_w: dead in reference
    const float* tm_value_w  = (const float*)d_in[6];
    const float* tm_recept_w = (const float*)d_in[7];
    const float* tm_out_w    = (const float*)d_in[8];
    const float* sa_q_w      = (const float*)d_in[9];
    const float* sa_q_b      = (const float*)d_in[10];
    const float* sa_k_w      = (const float*)d_in[11];
    const float* sa_k_b      = (const float*)d_in[12];
    const float* sa_v_w      = (const float*)d_in[13];
    const float* sa_v_b      = (const float*)d_in[14];
    const float* sa_o_w      = (const float*)d_in[15];
    const float* sa_o_b      = (const float*)d_in[16];
    const float* norm2_w     = (const float*)d_in[17];
    const float* cm_mix_k    = (const float*)d_in[18];
    const float* cm_mix_r    = (const float*)d_in[19];
    const float* cm_key_w    = (const float*)d_in[20];
    const float* cm_recept_w = (const float*)d_in[21];
    const float* cm_value_w  = (const float*)d_in[22];
    float* out = (float*)d_out;

    float *xn, *v, *r, *q, *kk, *vsa, *ao, *x1, *big;
    __nv_bfloat16 *pA1, *pA2, *pXN, *pBIG, *pQ, *pK, *wpk;
    cudaGetSymbolAddress((void**)&xn,   g_xn);
    cudaGetSymbolAddress((void**)&v,    g_v);
    cudaGetSymbolAddress((void**)&r,    g_r);
    cudaGetSymbolAddress((void**)&q,    g_q);
    cudaGetSymbolAddress((void**)&kk,   g_k);
    cudaGetSymbolAddress((void**)&vsa,  g_vsa);
    cudaGetSymbolAddress((void**)&ao,   g_ao);
    cudaGetSymbolAddress((void**)&x1,   g_x1);
    cudaGetSymbolAddress((void**)&big,  g_big);
    cudaGetSymbolAddress((void**)&pA1,  g_pA1);
    cudaGetSymbolAddress((void**)&pA2,  g_pA2);
    cudaGetSymbolAddress((void**)&pXN,  g_pXN);
    cudaGetSymbolAddress((void**)&pBIG, g_pBIG);
    cudaGetSymbolAddress((void**)&pQ,   g_pQ);
    cudaGetSymbolAddress((void**)&pK,   g_pK);
    cudaGetSymbolAddress((void**)&wpk,  g_wpk);

    cudaFuncSetAttribute(mma_gemm, cudaFuncAttributeMaxDynamicSharedMemorySize, MG_SMEM);

    const long ofsD  = (long)NT * Dm;     // activation plane size (D)
    const long ofsDI = (long)NT * DIm;
    const long ofsA  = (long)NT * Am;
    const long ofsW1 = (long)Dm * Dm;     // D x D weight plane
    const long ofsW4 = (long)DIm * Dm;    // cm_key / cm_value weight plane

    const dim3 gD (Dm / 256,  NT / 128);          // (4, 64)
    const dim3 gDI(DIm / 256, NT / 128);          // (16, 64)
    const dim3 gS (Sm / 256,  Sm / 128, Bb);      // (16, 32, 2)
    const dim3 gA (Am / 64,   NT / 64);
    const int  pairBlocks = NT * Dm / 512;

    auto wpack = [&](const float* w, long elems) {
        split_pack_pl<<<(unsigned)((elems / 2 + 255) / 256), 256>>>(w, wpk, elems / 2, elems);
    };

    // ---- time mix ----
    rmsnorm_k<<<NT, 256>>>(x, norm1_w, xn, pXN, ofsD);
    mix2pack_k<<<pairBlocks, 256>>>(xn, tm_mix_v, tm_mix_r, pA1, pA2, ofsD);

    wpack(tm_value_w, ofsW1);
    mma_gemm<<<gD, 256, MG_SMEM>>>(pA1, ofsD, wpk, ofsW1, v, Dm, Dm,
                                   0, 0, 0, nullptr, nullptr, 1.f, 0, 0, 0);

    wpack(tm_recept_w, ofsW1);
    mma_gemm<<<gD, 256, MG_SMEM>>>(pA2, ofsD, wpk, ofsW1, r, Dm, Dm,
                                   0, 0, 0, nullptr, nullptr, 1.f, 0, 0, 0);

    sgemm_nt<<<gA, 256>>>(xn, sa_q_w, q,  NT, Am, Dm, sa_q_b);
    sgemm_nt<<<gA, 256>>>(xn, sa_k_w, kk, NT, Am, Dm, sa_k_b);

    wpack(sa_v_w, ofsW1);
    mma_gemm<<<gD, 256, MG_SMEM>>>(pXN, ofsD, wpk, ofsW1, vsa, Dm, Dm,
                                   0, 0, 0, sa_v_b, nullptr, 1.f, 0, 0, 0);

    {
        long tq = (long)NT * Am / 2;
        split_pack_pl<<<(unsigned)((tq + 255) / 256), 256>>>(q,  pQ, tq, ofsA);
        split_pack_pl<<<(unsigned)((tq + 255) / 256), 256>>>(kk, pK, tq, ofsA);
    }
    mma_gemm<<<gS, 256, MG_SMEM>>>(pQ, ofsA, pK, ofsA, big, Sm, Am,
                                   (long)Sm * Am, (long)Sm * Am, (long)Sm * Sm,
                                   nullptr, nullptr, 0.125f, 0, 0, 0);

    topk_attn_k<<<NT, 128>>>(big, vsa, pA1, ofsD);

    wpack(sa_o_w, ofsW1);
    mma_gemm<<<gD, 256, MG_SMEM>>>(pA1, ofsD, wpk, ofsW1, ao, Dm, Dm,
                                   0, 0, 0, sa_o_b, nullptr, 1.f, 0, 0, 0);

    rkvpack_k<<<pairBlocks, 256>>>(r, ao, v, pA2, ofsD);

    wpack(tm_out_w, ofsW1);
    mma_gemm<<<gD, 256, MG_SMEM>>>(pA2, ofsD, wpk, ofsW1, x1, Dm, Dm,
                                   0, 0, 0, nullptr, x, 1.f, 0, 0, 0);

    // ---- channel mix ----
    rmsnorm_k<<<NT, 256>>>(x1, norm2_w, xn, nullptr, 0);
    mix2pack_k<<<pairBlocks, 256>>>(xn, cm_mix_k, cm_mix_r, pA1, pA2, ofsD);

    wpack(cm_key_w, ofsW4);
    mma_gemm<<<gDI, 256, MG_SMEM>>>(pA1, ofsD, wpk, ofsW4, (float*)pBIG, DIm, Dm,
                                    0, 0, 0, nullptr, nullptr, 1.f, 1, 1, ofsDI);

    wpack(cm_recept_w, ofsW1);
    mma_gemm<<<gD, 256, MG_SMEM>>>(pA2, ofsD, wpk, ofsW1, r, Dm, Dm,
                                   0, 0, 0, nullptr, nullptr, 1.f, 0, 0, 0);

    wpack(cm_value_w, ofsW4);
    mma_gemm<<<gD, 256, MG_SMEM>>>(pBIG, ofsDI, wpk, ofsW4, v, Dm, DIm,
                                   0, 0, 0, nullptr, nullptr, 1.f, 0, 0, 0);

    final_k<<<2 * pairBlocks, 256>>>(x1, r, v, out);
}

// round 12
// speedup vs baseline: 3.5173x; 1.0489x over previous
#include <cuda_runtime.h>
#include <cuda_bf16.h>
#include <math.h>
#include <stdint.h>

// Problem constants
#define Dm   1024
#define Sm   4096
#define Bb   2
#define DIm  4096
#define NT   (Bb*Sm)       // 8192 token rows
#define KTOP 32
#define Am   64

// ---------------------------------------------------------------------------
// Scratch. Packed operands: bf16 PLANES [hi (rows*K)][lo (rows*K)].
// g_pAct: 3 z-slots (stride 2*NT*Dm): slot0/slot1 = mix outputs, slot2 = xn.
// ---------------------------------------------------------------------------
__device__ float g_xn [NT*Dm];
__device__ float g_vrv[(size_t)3*NT*Dm];           // v | r | vsa (z-batched out)
__device__ float g_ao [NT*Dm];
__device__ float g_x1 [NT*Dm];
__device__ float g_qk [(size_t)NT*128];            // q||k fused projection
__device__ float g_big[(size_t)NT*Sm];             // scores
__device__ float g_b3 [3*Dm];                      // per-z bias for batched gemm
__device__ float g_qkb[128];                       // fused q/k bias
__device__ __align__(16) __nv_bfloat16 g_pAct[(size_t)6*NT*Dm];   // 3 slots x [hi|lo]
__device__ __align__(16) __nv_bfloat16 g_pBIG[(size_t)2*NT*DIm];
__device__ __align__(16) __nv_bfloat16 g_pQ  [(size_t)2*NT*Am];
__device__ __align__(16) __nv_bfloat16 g_pK  [(size_t)2*NT*Am];
__device__ __align__(16) __nv_bfloat16 g_wpk [(size_t)2*DIm*Dm];  // weight planes
__device__ __align__(16) __nv_bfloat16 g_wqk [(size_t)2*128*Dm];  // fused qk weights

// ---------------------------------------------------------------------------
// PTX helpers (legal at compute_103)
// ---------------------------------------------------------------------------
__device__ __forceinline__ uint32_t smem_u32(const void* p) {
    uint32_t a;
    asm("{ .reg .u64 t; cvta.to.shared.u64 t, %1; cvt.u32.u64 %0, t; }" : "=r"(a) : "l"(p));
    return a;
}
__device__ __forceinline__ uint32_t sw128(uint32_t o) { return o ^ ((o >> 3) & 0x70); }

__device__ __forceinline__ void cp16(uint32_t s, const void* g) {
    asm volatile("cp.async.cg.shared.global [%0], [%1], 16;" :: "r"(s), "l"(g));
}
__device__ __forceinline__ void cp_commit() { asm volatile("cp.async.commit_group;" ::: "memory"); }
__device__ __forceinline__ void cp_wait0()  { asm volatile("cp.async.wait_group 0;" ::: "memory"); }
__device__ __forceinline__ void cp_wait1()  { asm volatile("cp.async.wait_group 1;" ::: "memory"); }

__device__ __forceinline__ void ldsm4(uint32_t* r, uint32_t a) {
    asm volatile("ldmatrix.sync.aligned.m8n8.x4.shared.b16 {%0,%1,%2,%3}, [%4];"
                 : "=r"(r[0]), "=r"(r[1]), "=r"(r[2]), "=r"(r[3]) : "r"(a));
}
__device__ __forceinline__ void mma16816(float* c, const uint32_t* a, uint32_t b0, uint32_t b1) {
    asm volatile(
        "mma.sync.aligned.m16n8k16.row.col.f32.bf16.bf16.f32 "
        "{%0,%1,%2,%3}, {%4,%5,%6,%7}, {%8,%9}, {%0,%1,%2,%3};"
        : "+f"(c[0]), "+f"(c[1]), "+f"(c[2]), "+f"(c[3])
        : "r"(a[0]), "r"(a[1]), "r"(a[2]), "r"(a[3]), "r"(b0), "r"(b1));
}

__device__ __forceinline__ void split2(float v0, float v1,
                                       __nv_bfloat162& hp, __nv_bfloat162& lp) {
    __nv_bfloat16 h0 = __float2bfloat16_rn(v0);
    __nv_bfloat16 h1 = __float2bfloat16_rn(v1);
    __nv_bfloat16 l0 = __float2bfloat16_rn(v0 - __bfloat162float(h0));
    __nv_bfloat16 l1 = __float2bfloat16_rn(v1 - __bfloat162float(h1));
    hp.x = h0; hp.y = h1; lp.x = l0; lp.y = l1;
}

// ---------------------------------------------------------------------------
// mma.sync NT GEMM on hi/lo planes: C = alpha*(Ahi·Bhi + Alo·Bhi + Ahi·Blo)
// CTA tile 128xBN (BN=256 or 128), warp tile 64x(BN/4), BK=64, 2-stage.
// Requires M%128==0, N%BN==0, K%64==0.
// ---------------------------------------------------------------------------
template <int BN>
__global__ void __launch_bounds__(256, 1) mma_gemm(
    const __nv_bfloat16* __restrict__ Ap, long aLo,
    const __nv_bfloat16* __restrict__ Bp, long bLo,
    float* __restrict__ C, int N, int K,
    long sA, long sB, long sC,
    const float* __restrict__ bias, long sBias,
    const float* __restrict__ resid,
    float alpha, int relu2, int packout, long pOfs)
{
    constexpr int NTN = BN / 32;                   // acc n-tiles
    constexpr int NTP = BN / 64;                   // b ldsm groups
    constexpr uint32_t stALo = 16384u;
    constexpr uint32_t stBhi = 32768u;
    constexpr uint32_t stBlo = 32768u + BN * 128u;
    constexpr uint32_t stSz  = 32768u + 2u * BN * 128u;

    extern __shared__ char smem[];
    const __nv_bfloat16* Ahi = Ap + (long)blockIdx.z * sA;
    const __nv_bfloat16* Alo = Ap + aLo + (long)blockIdx.z * sA;
    const __nv_bfloat16* Bhi = Bp + (long)blockIdx.z * sB;
    const __nv_bfloat16* Blo = Bp + bLo + (long)blockIdx.z * sB;
    C += (long)blockIdx.z * sC;
    if (resid) resid += (long)blockIdx.z * sC;
    if (bias)  bias  += (long)blockIdx.z * sBias;

    const int tid  = threadIdx.x;
    const int lane = tid & 31;
    const int wid  = tid >> 5;
    const int wm   = wid >> 2;                    // 0..1
    const int wn   = wid & 3;                     // 0..3
    const int row0 = blockIdx.y * 128;
    const int col0 = blockIdx.x * BN;
    const uint32_t su = smem_u32(smem);

    float acc[4][NTN][4];
    #pragma unroll
    for (int mt = 0; mt < 4; mt++)
        #pragma unroll
        for (int nt = 0; nt < NTN; nt++)
            #pragma unroll
            for (int i = 0; i < 4; i++) acc[mt][nt][i] = 0.f;

    const int nch = K >> 6;

    auto load_stage = [&](uint32_t sbase, int k0) {
        #pragma unroll
        for (int i = 0; i < 4; i++) {
            int j = tid + 256 * i; int r = j >> 3, cb = (j & 7) << 4;
            cp16(sbase + sw128((uint32_t)(r * 128 + cb)),
                 Ahi + (long)(row0 + r) * K + k0 + (cb >> 1));
        }
        #pragma unroll
        for (int i = 0; i < 4; i++) {
            int j = tid + 256 * i; int r = j >> 3, cb = (j & 7) << 4;
            cp16(sbase + stALo + sw128((uint32_t)(r * 128 + cb)),
                 Alo + (long)(row0 + r) * K + k0 + (cb >> 1));
        }
        #pragma unroll
        for (int i = 0; i < BN / 32; i++) {
            int j = tid + 256 * i; int r = j >> 3, cb = (j & 7) << 4;
            cp16(sbase + stBhi + sw128((uint32_t)(r * 128 + cb)),
                 Bhi + (long)(col0 + r) * K + k0 + (cb >> 1));
        }
        #pragma unroll
        for (int i = 0; i < BN / 32; i++) {
            int j = tid + 256 * i; int r = j >> 3, cb = (j & 7) << 4;
            cp16(sbase + stBlo + sw128((uint32_t)(r * 128 + cb)),
                 Blo + (long)(col0 + r) * K + k0 + (cb >> 1));
        }
    };

    load_stage(su, 0);
    cp_commit();

    for (int t = 0; t < nch; t++) {
        if (t + 1 < nch) {
            load_stage(su + (((t + 1) & 1) ? stSz : 0u), (t + 1) << 6);
            cp_commit();
            cp_wait1();
        } else {
            cp_wait0();
        }
        __syncthreads();

        const uint32_t sb  = su + ((t & 1) ? stSz : 0u);
        const uint32_t sAh = sb;
        const uint32_t sAl = sb + stALo;
        const uint32_t sBh = sb + stBhi;
        const uint32_t sBl = sb + stBlo;

        #pragma unroll
        for (int ks = 0; ks < 4; ks++) {
            uint32_t ahi[4][4], alo[4][4];
            #pragma unroll
            for (int mt = 0; mt < 4; mt++) {
                uint32_t off = (uint32_t)((wm * 64 + mt * 16 + (lane & 15)) * 128
                                          + ks * 32 + ((lane >> 4) << 4));
                ldsm4(ahi[mt], sAh + sw128(off));
                ldsm4(alo[mt], sAl + sw128(off));
            }
            #pragma unroll
            for (int ntp = 0; ntp < NTP; ntp++) {
                int g = lane >> 3;
                uint32_t off = (uint32_t)((wn * (BN / 4) + ntp * 16 + (lane & 7) + (g >> 1) * 8) * 128
                                          + ks * 32 + (g & 1) * 16);
                uint32_t bh[4], bl[4];
                ldsm4(bh, sBh + sw128(off));
                ldsm4(bl, sBl + sw128(off));
                #pragma unroll
                for (int s = 0; s < 2; s++) {
                    int nt = ntp * 2 + s;
                    uint32_t b0h = bh[2 * s], b1h = bh[2 * s + 1];
                    uint32_t b0l = bl[2 * s], b1l = bl[2 * s + 1];
                    #pragma unroll
                    for (int mt = 0; mt < 4; mt++) {
                        mma16816(acc[mt][nt], ahi[mt], b0h, b1h);
                        mma16816(acc[mt][nt], alo[mt], b0h, b1h);
                        mma16816(acc[mt][nt], ahi[mt], b0l, b1l);
                    }
                }
            }
        }
        __syncthreads();
    }

    // epilogue
    #pragma unroll
    for (int mt = 0; mt < 4; mt++) {
        int gr0 = row0 + wm * 64 + mt * 16 + (lane >> 2);
        #pragma unroll
        for (int nt = 0; nt < NTN; nt++) {
            int gc = col0 + wn * (BN / 4) + nt * 8 + ((lane & 3) << 1);
            float b0 = 0.f, b1 = 0.f;
            if (bias) { b0 = bias[gc]; b1 = bias[gc + 1]; }
            #pragma unroll
            for (int h = 0; h < 2; h++) {
                int gr = gr0 + h * 8;
                float v0 = acc[mt][nt][h * 2 + 0] * alpha + b0;
                float v1 = acc[mt][nt][h * 2 + 1] * alpha + b1;
                if (relu2) { v0 = fmaxf(v0, 0.f); v0 *= v0;
                             v1 = fmaxf(v1, 0.f); v1 *= v1; }
                if (resid) {
                    float2 rr = *reinterpret_cast<const float2*>(resid + (long)gr * N + gc);
                    v0 += rr.x; v1 += rr.y;
                }
                if (packout) {
                    __nv_bfloat16* P = reinterpret_cast<__nv_bfloat16*>(C);
                    long base = (long)gr * N + gc;
                    __nv_bfloat162 hp, lp;
                    split2(v0, v1, hp, lp);
                    *reinterpret_cast<__nv_bfloat162*>(P + base)        = hp;
                    *reinterpret_cast<__nv_bfloat162*>(P + base + pOfs) = lp;
                } else {
                    *reinterpret_cast<float2*>(C + (long)gr * N + gc) = make_float2(v0, v1);
                }
            }
        }
    }
}

// ---------------------------------------------------------------------------
// packers / small fills
// ---------------------------------------------------------------------------
__global__ void __launch_bounds__(256) split_pack_pl(
    const float* __restrict__ src, __nv_bfloat16* __restrict__ dst,
    long total2, long planeOfs)
{
    long i = (long)blockIdx.x * 256 + threadIdx.x;
    if (i >= total2) return;
    long e = i << 1;
    float2 x = *reinterpret_cast<const float2*>(src + e);
    __nv_bfloat162 hp, lp;
    split2(x.x, x.y, hp, lp);
    *reinterpret_cast<__nv_bfloat162*>(dst + e)            = hp;
    *reinterpret_cast<__nv_bfloat162*>(dst + planeOfs + e) = lp;
}

__global__ void __launch_bounds__(256) fill_b3(
    const float* __restrict__ vb, float* __restrict__ b3)
{
    int i = blockIdx.x * 256 + threadIdx.x;
    if (i < 3 * Dm) b3[i] = (i < 2 * Dm) ? 0.f : vb[i - 2 * Dm];
}

__global__ void __launch_bounds__(128) fill_qkb(
    const float* __restrict__ qb, const float* __restrict__ kb, float* __restrict__ o)
{
    int i = threadIdx.x;
    o[i] = (i < 64) ? qb[i] : kb[i - 64];
}

// split fused qk buffer -> pQ (A planes) and pK (B planes)
__global__ void __launch_bounds__(256) pack_qk(
    const float* __restrict__ qk, __nv_bfloat16* __restrict__ pQ,
    __nv_bfloat16* __restrict__ pK, long planeOfs)
{
    long i2 = (long)blockIdx.x * 256 + threadIdx.x;
    long idx = i2 << 1;                         // element index within NT*64
    if (idx >= (long)NT * Am) return;
    long row = idx >> 6;
    int  c = (int)(idx & 63);
    float2 qv = *reinterpret_cast<const float2*>(qk + row * 128 + c);
    float2 kv = *reinterpret_cast<const float2*>(qk + row * 128 + 64 + c);
    __nv_bfloat162 hp, lp;
    long e = row * Am + c;
    split2(qv.x, qv.y, hp, lp);
    *reinterpret_cast<__nv_bfloat162*>(pQ + e)            = hp;
    *reinterpret_cast<__nv_bfloat162*>(pQ + planeOfs + e) = lp;
    split2(kv.x, kv.y, hp, lp);
    *reinterpret_cast<__nv_bfloat162*>(pK + e)            = hp;
    *reinterpret_cast<__nv_bfloat162*>(pK + planeOfs + e) = lp;
}

// ---------------------------------------------------------------------------
// rmsnorm: fp32 out + optional hi/lo plane out
// ---------------------------------------------------------------------------
__global__ void __launch_bounds__(256) rmsnorm_k(
    const float* __restrict__ x, const float* __restrict__ w,
    float* __restrict__ out, __nv_bfloat16* __restrict__ pk, long planeOfs)
{
    int row = blockIdx.x;
    const float* xr = x + (long)row * Dm;
    int tid = threadIdx.x;
    float ss = 0.f;
    #pragma unroll
    for (int d = tid; d < Dm; d += 256) { float v = xr[d]; ss += v * v; }
    __shared__ float red[256];
    red[tid] = ss; __syncthreads();
    for (int o = 128; o; o >>= 1) {
        if (tid < o) red[tid] += red[tid + o];
        __syncthreads();
    }
    float scale = 1.f / (sqrtf(red[0] * (1.f / Dm)) + 1e-8f);
    #pragma unroll
    for (int d = tid; d < Dm; d += 256) {
        float v = w[d] * xr[d] * scale;
        long e = (long)row * Dm + d;
        out[e] = v;
        if (pk) {
            __nv_bfloat16 h = __float2bfloat16_rn(v);
            __nv_bfloat16 l = __float2bfloat16_rn(v - __bfloat162float(h));
            pk[e] = h; pk[e + planeOfs] = l;
        }
    }
}

// ---------------------------------------------------------------------------
// token-shift mixes -> two hi/lo-plane packed A operands
// ---------------------------------------------------------------------------
__global__ void __launch_bounds__(256) mix2pack_k(
    const float* __restrict__ xn, const float* __restrict__ m1,
    const float* __restrict__ m2,
    __nv_bfloat16* __restrict__ p1, __nv_bfloat16* __restrict__ p2, long planeOfs)
{
    long pi2 = (long)blockIdx.x * 256 + threadIdx.x;
    long i = pi2 << 1;
    int d = (int)(i & (Dm - 1));
    int s = (int)((i >> 10) & (Sm - 1));
    long prev = s ? (i - Dm) : i;
    float2 cur = *reinterpret_cast<const float2*>(xn + i);
    float2 prv = *reinterpret_cast<const float2*>(xn + prev);
    float a0 = m1[d], a1 = m1[d + 1];
    float b0 = m2[d], b1 = m2[d + 1];
    float o10 = cur.x * a0 + prv.x * (1.f - a0);
    float o11 = cur.y * a1 + prv.y * (1.f - a1);
    float o20 = cur.x * b0 + prv.x * (1.f - b0);
    float o21 = cur.y * b1 + prv.y * (1.f - b1);
    __nv_bfloat162 hp, lp;
    split2(o10, o11, hp, lp);
    *reinterpret_cast<__nv_bfloat162*>(p1 + i)            = hp;
    *reinterpret_cast<__nv_bfloat162*>(p1 + planeOfs + i) = lp;
    split2(o20, o21, hp, lp);
    *reinterpret_cast<__nv_bfloat162*>(p2 + i)            = hp;
    *reinterpret_cast<__nv_bfloat162*>(p2 + planeOfs + i) = lp;
}

// ---------------------------------------------------------------------------
// top-32 (owner-rescan) + softmax + V-gather -> hi/lo planes
// ---------------------------------------------------------------------------
__global__ void __launch_bounds__(128) topk_attn_k(
    const float* __restrict__ Sc, const float* __restrict__ Vsa,
    __nv_bfloat16* __restrict__ OutP, long planeOfs)
{
    int q = blockIdx.x;
    int b = q >> 12;
    const float* srow = Sc + (long)q * Sm;

    __shared__ float topv[KTOP];
    __shared__ int   topi[KTOP];
    __shared__ float wmv[4];
    __shared__ int   wiv[4];
    __shared__ int   sel;
    __shared__ float p[KTOP];

    const int tid  = threadIdx.x;
    const int lane = tid & 31;
    const int wrp  = tid >> 5;

    float sv[32];
    #pragma unroll
    for (int i = 0; i < 32; i++) sv[i] = srow[tid + (i << 7)];

    float best = -INFINITY; int bloc = 0;
    #pragma unroll
    for (int i = 0; i < 32; i++)
        if (sv[i] > best) { best = sv[i]; bloc = i; }

    for (int it = 0; it < KTOP; it++) {
        float cb = best;
        int   ci = tid + (bloc << 7);
        #pragma unroll
        for (int o = 16; o; o >>= 1) {
            float ov = __shfl_down_sync(0xffffffffu, cb, o);
            int   oi = __shfl_down_sync(0xffffffffu, ci, o);
            if (ov > cb || (ov == cb && oi < ci)) { cb = ov; ci = oi; }
        }
        if (lane == 0) { wmv[wrp] = cb; wiv[wrp] = ci; }
        __syncthreads();
        if (tid == 0) {
            float bb = wmv[0]; int bj = wiv[0];
            #pragma unroll
            for (int w2 = 1; w2 < 4; w2++)
                if (wmv[w2] > bb || (wmv[w2] == bb && wiv[w2] < bj)) { bb = wmv[w2]; bj = wiv[w2]; }
            topv[it] = bb; topi[it] = bj; sel = bj;
        }
        __syncthreads();
        int bj = sel;
        if ((bj & 127) == tid) {
            sv[bj >> 7] = -INFINITY;
            best = -INFINITY; bloc = 0;
            #pragma unroll
            for (int i = 0; i < 32; i++)
                if (sv[i] > best) { best = sv[i]; bloc = i; }
        }
        __syncthreads();
    }

    if (tid == 0) {
        float mx = topv[0], Z = 0.f;
        #pragma unroll
        for (int i2 = 0; i2 < KTOP; i2++) { float e = expf(topv[i2] - mx); p[i2] = e; Z += e; }
        float iz = 1.f / Z;
        #pragma unroll
        for (int i2 = 0; i2 < KTOP; i2++) p[i2] *= iz;
    }
    __syncthreads();

    const float* Vb = Vsa + (long)b * Sm * Dm;
    for (int d = tid; d < Dm; d += 128) {
        float acc = 0.f;
        #pragma unroll
        for (int i2 = 0; i2 < KTOP; i2++)
            acc += p[i2] * Vb[(long)topi[i2] * Dm + d];
        __nv_bfloat16 h = __float2bfloat16_rn(acc);
        __nv_bfloat16 l = __float2bfloat16_rn(acc - __bfloat162float(h));
        long e = (long)q * Dm + d;
        OutP[e] = h; OutP[e + planeOfs] = l;
    }
}

// ---------------------------------------------------------------------------
// gates
// ---------------------------------------------------------------------------
__global__ void __launch_bounds__(256) rkvpack_k(
    const float* __restrict__ r, const float* __restrict__ ao,
    const float* __restrict__ v, __nv_bfloat16* __restrict__ p1, long planeOfs)
{
    long pi2 = (long)blockIdx.x * 256 + threadIdx.x;
    long i = pi2 << 1;
    float2 rr = *reinterpret_cast<const float2*>(r + i);
    float2 aa = *reinterpret_cast<const float2*>(ao + i);
    float2 vv = *reinterpret_cast<const float2*>(v + i);
    float o0 = (1.f / (1.f + expf(-rr.x))) * (aa.x + vv.x);
    float o1 = (1.f / (1.f + expf(-rr.y))) * (aa.y + vv.y);
    __nv_bfloat162 hp, lp;
    split2(o0, o1, hp, lp);
    *reinterpret_cast<__nv_bfloat162*>(p1 + i)            = hp;
    *reinterpret_cast<__nv_bfloat162*>(p1 + planeOfs + i) = lp;
}

__global__ void __launch_bounds__(256) final_k(
    const float* __restrict__ x1, const float* __restrict__ r2,
    const float* __restrict__ kv, float* __restrict__ o)
{
    long i = (long)blockIdx.x * 256 + threadIdx.x;
    float sig = 1.f / (1.f + expf(-r2[i]));
    o[i] = x1[i] + sig * kv[i];
}

// ---------------------------------------------------------------------------
// launcher
// ---------------------------------------------------------------------------
extern "C" void kernel_launch(void* const* d_in, const int* in_sizes, int n_in,
                              void* d_out, int out_size)
{
    const float* x           = (const float*)d_in[0];
    const float* norm1_w     = (const float*)d_in[1];
    const float* tm_mix_v    = (const float*)d_in[3];
    const float* tm_mix_r    = (const float*)d_in[4];
    // d_in[2]=tm_mix_k, d_in[5]=tm_key_w: dead in reference
    const float* tm_value_w  = (const float*)d_in[6];
    const float* tm_recept_w = (const float*)d_in[7];
    const float* tm_out_w    = (const float*)d_in[8];
    const float* sa_q_w      = (const float*)d_in[9];
    const float* sa_q_b      = (const float*)d_in[10];
    const float* sa_k_w      = (const float*)d_in[11];
    const float* sa_k_b      = (const float*)d_in[12];
    const float* sa_v_w      = (const float*)d_in[13];
    const float* sa_v_b      = (const float*)d_in[14];
    const float* sa_o_w      = (const float*)d_in[15];
    const float* sa_o_b      = (const float*)d_in[16];
    const float* norm2_w     = (const float*)d_in[17];
    const float* cm_mix_k    = (const float*)d_in[18];
    const float* cm_mix_r    = (const float*)d_in[19];
    const float* cm_key_w    = (const float*)d_in[20];
    const float* cm_recept_w = (const float*)d_in[21];
    const float* cm_value_w  = (const float*)d_in[22];
    float* out = (float*)d_out;

    float *xn, *vrv, *ao, *x1, *qk, *big, *b3, *qkb;
    __nv_bfloat16 *pAct, *pBIG, *pQ, *pK, *wpk, *wqk;
    cudaGetSymbolAddress((void**)&xn,   g_xn);
    cudaGetSymbolAddress((void**)&vrv,  g_vrv);
    cudaGetSymbolAddress((void**)&ao,   g_ao);
    cudaGetSymbolAddress((void**)&x1,   g_x1);
    cudaGetSymbolAddress((void**)&qk,   g_qk);
    cudaGetSymbolAddress((void**)&big,  g_big);
    cudaGetSymbolAddress((void**)&b3,   g_b3);
    cudaGetSymbolAddress((void**)&qkb,  g_qkb);
    cudaGetSymbolAddress((void**)&pAct, g_pAct);
    cudaGetSymbolAddress((void**)&pBIG, g_pBIG);
    cudaGetSymbolAddress((void**)&pQ,   g_pQ);
    cudaGetSymbolAddress((void**)&pK,   g_pK);
    cudaGetSymbolAddress((void**)&wpk,  g_wpk);
    cudaGetSymbolAddress((void**)&wqk,  g_wqk);

    cudaFuncSetAttribute(mma_gemm<256>, cudaFuncAttributeMaxDynamicSharedMemorySize, 196608);
    cudaFuncSetAttribute(mma_gemm<128>, cudaFuncAttributeMaxDynamicSharedMemorySize, 131072);

    const long ofsD  = (long)NT * Dm;            // activation plane size
    const long ofsDI = (long)NT * DIm;
    const long ofsA  = (long)NT * Am;
    const long slot  = 2 * ofsD;                 // z-slot stride in pAct
    const long wslot = 2L * Dm * Dm;             // z-slot stride in wpk
    __nv_bfloat16* pS0 = pAct;                   // mix1 / att / cm mix1
    __nv_bfloat16* pS1 = pAct + slot;            // mix2 / rkv / cm mix2
    __nv_bfloat16* pS2 = pAct + 2 * slot;        // xn packed

    const dim3 gD (Dm / 256,  NT / 128);          // (4, 64)
    const dim3 gD3(Dm / 256,  NT / 128, 3);       // batched v/r/vsa
    const dim3 gDI(DIm / 256, NT / 128);          // (16, 64)
    const dim3 gS (Sm / 256,  Sm / 128, Bb);      // (16, 32, 2)
    const dim3 gQK(1, NT / 128);                  // fused q/k, BN=128
    const int  pairBlocks = NT * Dm / 512;
    const int  wDDblocks  = (int)((Dm * (long)Dm / 2 + 255) / 256);
    const int  wDIblocks  = (int)((DIm * (long)Dm / 2 + 255) / 256);

    // ---- time mix ----
    rmsnorm_k<<<NT, 256>>>(x, norm1_w, xn, pS2, ofsD);
    mix2pack_k<<<pairBlocks, 256>>>(xn, tm_mix_v, tm_mix_r, pS0, pS1, ofsD);

    // batched v / r / vsa
    split_pack_pl<<<wDDblocks, 256>>>(tm_value_w,  wpk,              Dm * (long)Dm / 2, (long)Dm * Dm);
    split_pack_pl<<<wDDblocks, 256>>>(tm_recept_w, wpk + wslot,      Dm * (long)Dm / 2, (long)Dm * Dm);
    split_pack_pl<<<wDDblocks, 256>>>(sa_v_w,      wpk + 2 * wslot,  Dm * (long)Dm / 2, (long)Dm * Dm);
    fill_b3<<<(3 * Dm + 255) / 256, 256>>>(sa_v_b, b3);
    mma_gemm<256><<<gD3, 256, 196608>>>(pAct, ofsD, wpk, (long)Dm * Dm, vrv, Dm, Dm,
                                        slot, wslot, ofsD, b3, Dm, nullptr, 1.f, 0, 0, 0);
    float* v   = vrv;
    float* r   = vrv + ofsD;
    float* vsa = vrv + 2 * ofsD;

    // fused q/k projection on tensor path (BN=128)
    split_pack_pl<<<(int)((64L * Dm / 2 + 255) / 256), 256>>>(sa_q_w, wqk,            64L * Dm / 2, 128L * Dm);
    split_pack_pl<<<(int)((64L * Dm / 2 + 255) / 256), 256>>>(sa_k_w, wqk + 64 * Dm,  64L * Dm / 2, 128L * Dm);
    fill_qkb<<<1, 128>>>(sa_q_b, sa_k_b, qkb);
    mma_gemm<128><<<gQK, 256, 131072>>>(pS2, ofsD, wqk, 128L * Dm, qk, 128, Dm,
                                        0, 0, 0, qkb, 0, nullptr, 1.f, 0, 0, 0);
    pack_qk<<<(int)((ofsA / 2 + 255) / 256), 256>>>(qk, pQ, pK, ofsA);

    // scores
    mma_gemm<256><<<gS, 256, 196608>>>(pQ, ofsA, pK, ofsA, big, Sm, Am,
                                       (long)Sm * Am, (long)Sm * Am, (long)Sm * Sm,
                                       nullptr, 0, nullptr, 0.125f, 0, 0, 0);

    topk_attn_k<<<NT, 128>>>(big, vsa, pS0, ofsD);

    split_pack_pl<<<wDDblocks, 256>>>(sa_o_w, wpk, Dm * (long)Dm / 2, (long)Dm * Dm);
    mma_gemm<256><<<gD, 256, 196608>>>(pS0, ofsD, wpk, (long)Dm * Dm, ao, Dm, Dm,
                                       0, 0, 0, sa_o_b, 0, nullptr, 1.f, 0, 0, 0);

    rkvpack_k<<<pairBlocks, 256>>>(r, ao, v, pS1, ofsD);

    split_pack_pl<<<wDDblocks, 256>>>(tm_out_w, wpk, Dm * (long)Dm / 2, (long)Dm * Dm);
    mma_gemm<256><<<gD, 256, 196608>>>(pS1, ofsD, wpk, (long)Dm * Dm, x1, Dm, Dm,
                                       0, 0, 0, nullptr, 0, x, 1.f, 0, 0, 0);

    // ---- channel mix ----
    rmsnorm_k<<<NT, 256>>>(x1, norm2_w, xn, nullptr, 0);
    mix2pack_k<<<pairBlocks, 256>>>(xn, cm_mix_k, cm_mix_r, pS0, pS1, ofsD);

    split_pack_pl<<<wDIblocks, 256>>>(cm_key_w, wpk, DIm * (long)Dm / 2, (long)DIm * Dm);
    mma_gemm<256><<<gDI, 256, 196608>>>(pS0, ofsD, wpk, (long)DIm * Dm, (float*)pBIG, DIm, Dm,
                                        0, 0, 0, nullptr, 0, nullptr, 1.f, 1, 1, ofsDI);

    split_pack_pl<<<wDDblocks, 256>>>(cm_recept_w, wpk, Dm * (long)Dm / 2, (long)Dm * Dm);
    mma_gemm<256><<<gD, 256, 196608>>>(pS1, ofsD, wpk, (long)Dm * Dm, r, Dm, Dm,
                                       0, 0, 0, nullptr, 0, nullptr, 1.f, 0, 0, 0);

    split_pack_pl<<<wDIblocks, 256>>>(cm_value_w, wpk, DIm * (long)Dm / 2, (long)DIm * Dm);
    mma_gemm<256><<<gD, 256, 196608>>>(pBIG, ofsDI, wpk, (long)DIm * Dm, v, Dm, DIm,
                                       0, 0, 0, nullptr, 0, nullptr, 1.f, 0, 0, 0);

    final_k<<<2 * pairBlocks, 256>>>(x1, r, v, out);
}

// round 13
// speedup vs baseline: 3.5254x; 1.0023x over previous
#include <cuda_runtime.h>
#include <cuda_bf16.h>
#include <math.h>
#include <stdint.h>

// Problem constants
#define Dm   1024
#define Sm   4096
#define Bb   2
#define DIm  4096
#define NT   (Bb*Sm)       // 8192 token rows
#define KTOP 32
#define Am   64

// ---------------------------------------------------------------------------
// Scratch. Packed operands: bf16 PLANES [hi (rows*K)][lo (rows*K)].
// ---------------------------------------------------------------------------
__device__ float g_xn [NT*Dm];
__device__ float g_vrv[(size_t)3*NT*Dm];           // v | r | vsa (z-batched out)
__device__ float g_ao [NT*Dm];
__device__ float g_x1 [NT*Dm];
__device__ float g_qk [(size_t)NT*128];            // q||k fused projection
__device__ float g_big[(size_t)NT*Sm];             // scores
__device__ float g_b3 [3*Dm];                      // per-z bias for batched gemm
__device__ float g_qkb[128];                       // fused q/k bias
__device__ __align__(16) __nv_bfloat16 g_pAct[(size_t)6*NT*Dm];   // 3 slots x [hi|lo]
__device__ __align__(16) __nv_bfloat16 g_pBIG[(size_t)2*NT*DIm];
__device__ __align__(16) __nv_bfloat16 g_pQ  [(size_t)2*NT*Am];
__device__ __align__(16) __nv_bfloat16 g_pK  [(size_t)2*NT*Am];
__device__ __align__(16) __nv_bfloat16 g_wpk [(size_t)2*DIm*Dm];  // weight planes
__device__ __align__(16) __nv_bfloat16 g_wqk [(size_t)2*128*Dm];  // fused qk weights

// ---------------------------------------------------------------------------
// PTX helpers (legal at compute_103)
// ---------------------------------------------------------------------------
__device__ __forceinline__ uint32_t smem_u32(const void* p) {
    uint32_t a;
    asm("{ .reg .u64 t; cvta.to.shared.u64 t, %1; cvt.u32.u64 %0, t; }" : "=r"(a) : "l"(p));
    return a;
}
__device__ __forceinline__ uint32_t sw128(uint32_t o) { return o ^ ((o >> 3) & 0x70); }

__device__ __forceinline__ void cp16(uint32_t s, const void* g) {
    asm volatile("cp.async.cg.shared.global [%0], [%1], 16;" :: "r"(s), "l"(g));
}
__device__ __forceinline__ void cp_commit() { asm volatile("cp.async.commit_group;" ::: "memory"); }
__device__ __forceinline__ void cp_wait0()  { asm volatile("cp.async.wait_group 0;" ::: "memory"); }
__device__ __forceinline__ void cp_wait1()  { asm volatile("cp.async.wait_group 1;" ::: "memory"); }

__device__ __forceinline__ void ldsm4(uint32_t* r, uint32_t a) {
    asm volatile("ldmatrix.sync.aligned.m8n8.x4.shared.b16 {%0,%1,%2,%3}, [%4];"
                 : "=r"(r[0]), "=r"(r[1]), "=r"(r[2]), "=r"(r[3]) : "r"(a));
}
__device__ __forceinline__ void mma16816(float* c, const uint32_t* a, uint32_t b0, uint32_t b1) {
    asm volatile(
        "mma.sync.aligned.m16n8k16.row.col.f32.bf16.bf16.f32 "
        "{%0,%1,%2,%3}, {%4,%5,%6,%7}, {%8,%9}, {%0,%1,%2,%3};"
        : "+f"(c[0]), "+f"(c[1]), "+f"(c[2]), "+f"(c[3])
        : "r"(a[0]), "r"(a[1]), "r"(a[2]), "r"(a[3]), "r"(b0), "r"(b1));
}

__device__ __forceinline__ void split2(float v0, float v1,
                                       __nv_bfloat162& hp, __nv_bfloat162& lp) {
    __nv_bfloat16 h0 = __float2bfloat16_rn(v0);
    __nv_bfloat16 h1 = __float2bfloat16_rn(v1);
    __nv_bfloat16 l0 = __float2bfloat16_rn(v0 - __bfloat162float(h0));
    __nv_bfloat16 l1 = __float2bfloat16_rn(v1 - __bfloat162float(h1));
    hp.x = h0; hp.y = h1; lp.x = l0; lp.y = l1;
}

// ---------------------------------------------------------------------------
// mma.sync NT GEMM on hi/lo planes: C = alpha*(Ahi·Bhi + Alo·Bhi + Ahi·Blo)
// CTA tile 128xBN (BN=256 or 128), warp tile 64x(BN/4), BK=64, 2-stage.
// Term-outer MMA ordering: RAW distance 8 between accumulator reuses.
// ---------------------------------------------------------------------------
template <int BN>
__global__ void __launch_bounds__(256, 1) mma_gemm(
    const __nv_bfloat16* __restrict__ Ap, long aLo,
    const __nv_bfloat16* __restrict__ Bp, long bLo,
    float* __restrict__ C, int N, int K,
    long sA, long sB, long sC,
    const float* __restrict__ bias, long sBias,
    const float* __restrict__ resid,
    float alpha, int relu2, int packout, long pOfs)
{
    constexpr int NTN = BN / 32;                   // acc n-tiles
    constexpr int NTP = BN / 64;                   // b ldsm groups
    constexpr uint32_t stALo = 16384u;
    constexpr uint32_t stBhi = 32768u;
    constexpr uint32_t stBlo = 32768u + BN * 128u;
    constexpr uint32_t stSz  = 32768u + 2u * BN * 128u;

    extern __shared__ char smem[];
    const __nv_bfloat16* Ahi = Ap + (long)blockIdx.z * sA;
    const __nv_bfloat16* Alo = Ap + aLo + (long)blockIdx.z * sA;
    const __nv_bfloat16* Bhi = Bp + (long)blockIdx.z * sB;
    const __nv_bfloat16* Blo = Bp + bLo + (long)blockIdx.z * sB;
    C += (long)blockIdx.z * sC;
    if (resid) resid += (long)blockIdx.z * sC;
    if (bias)  bias  += (long)blockIdx.z * sBias;

    const int tid  = threadIdx.x;
    const int lane = tid & 31;
    const int wid  = tid >> 5;
    const int wm   = wid >> 2;                    // 0..1
    const int wn   = wid & 3;                     // 0..3
    const int row0 = blockIdx.y * 128;
    const int col0 = blockIdx.x * BN;
    const uint32_t su = smem_u32(smem);

    float acc[4][NTN][4];
    #pragma unroll
    for (int mt = 0; mt < 4; mt++)
        #pragma unroll
        for (int nt = 0; nt < NTN; nt++)
            #pragma unroll
            for (int i = 0; i < 4; i++) acc[mt][nt][i] = 0.f;

    const int nch = K >> 6;

    auto load_stage = [&](uint32_t sbase, int k0) {
        #pragma unroll
        for (int i = 0; i < 4; i++) {
            int j = tid + 256 * i; int r = j >> 3, cb = (j & 7) << 4;
            cp16(sbase + sw128((uint32_t)(r * 128 + cb)),
                 Ahi + (long)(row0 + r) * K + k0 + (cb >> 1));
        }
        #pragma unroll
        for (int i = 0; i < 4; i++) {
            int j = tid + 256 * i; int r = j >> 3, cb = (j & 7) << 4;
            cp16(sbase + stALo + sw128((uint32_t)(r * 128 + cb)),
                 Alo + (long)(row0 + r) * K + k0 + (cb >> 1));
        }
        #pragma unroll
        for (int i = 0; i < BN / 32; i++) {
            int j = tid + 256 * i; int r = j >> 3, cb = (j & 7) << 4;
            cp16(sbase + stBhi + sw128((uint32_t)(r * 128 + cb)),
                 Bhi + (long)(col0 + r) * K + k0 + (cb >> 1));
        }
        #pragma unroll
        for (int i = 0; i < BN / 32; i++) {
            int j = tid + 256 * i; int r = j >> 3, cb = (j & 7) << 4;
            cp16(sbase + stBlo + sw128((uint32_t)(r * 128 + cb)),
                 Blo + (long)(col0 + r) * K + k0 + (cb >> 1));
        }
    };

    load_stage(su, 0);
    cp_commit();

    for (int t = 0; t < nch; t++) {
        if (t + 1 < nch) {
            load_stage(su + (((t + 1) & 1) ? stSz : 0u), (t + 1) << 6);
            cp_commit();
            cp_wait1();
        } else {
            cp_wait0();
        }
        __syncthreads();

        const uint32_t sb  = su + ((t & 1) ? stSz : 0u);
        const uint32_t sAh = sb;
        const uint32_t sAl = sb + stALo;
        const uint32_t sBh = sb + stBhi;
        const uint32_t sBl = sb + stBlo;

        #pragma unroll
        for (int ks = 0; ks < 4; ks++) {
            uint32_t ahi[4][4], alo[4][4];
            #pragma unroll
            for (int mt = 0; mt < 4; mt++) {
                uint32_t off = (uint32_t)((wm * 64 + mt * 16 + (lane & 15)) * 128
                                          + ks * 32 + ((lane >> 4) << 4));
                ldsm4(ahi[mt], sAh + sw128(off));
                ldsm4(alo[mt], sAl + sw128(off));
            }
            #pragma unroll
            for (int ntp = 0; ntp < NTP; ntp++) {
                int g = lane >> 3;
                uint32_t off = (uint32_t)((wn * (BN / 4) + ntp * 16 + (lane & 7) + (g >> 1) * 8) * 128
                                          + ks * 32 + (g & 1) * 16);
                uint32_t bh[4], bl[4];
                ldsm4(bh, sBh + sw128(off));
                ldsm4(bl, sBl + sw128(off));
                // term-outer ordering: each term sweeps all 8 (s, mt) accs
                // before any acc is reused -> RAW distance 8 MMA issues.
                #pragma unroll
                for (int s = 0; s < 2; s++)
                    #pragma unroll
                    for (int mt = 0; mt < 4; mt++)
                        mma16816(acc[mt][ntp * 2 + s], ahi[mt], bh[2 * s], bh[2 * s + 1]);
                #pragma unroll
                for (int s = 0; s < 2; s++)
                    #pragma unroll
                    for (int mt = 0; mt < 4; mt++)
                        mma16816(acc[mt][ntp * 2 + s], alo[mt], bh[2 * s], bh[2 * s + 1]);
                #pragma unroll
                for (int s = 0; s < 2; s++)
                    #pragma unroll
                    for (int mt = 0; mt < 4; mt++)
                        mma16816(acc[mt][ntp * 2 + s], ahi[mt], bl[2 * s], bl[2 * s + 1]);
            }
        }
        __syncthreads();
    }

    // epilogue
    #pragma unroll
    for (int mt = 0; mt < 4; mt++) {
        int gr0 = row0 + wm * 64 + mt * 16 + (lane >> 2);
        #pragma unroll
        for (int nt = 0; nt < NTN; nt++) {
            int gc = col0 + wn * (BN / 4) + nt * 8 + ((lane & 3) << 1);
            float b0 = 0.f, b1 = 0.f;
            if (bias) { b0 = bias[gc]; b1 = bias[gc + 1]; }
            #pragma unroll
            for (int h = 0; h < 2; h++) {
                int gr = gr0 + h * 8;
                float v0 = acc[mt][nt][h * 2 + 0] * alpha + b0;
                float v1 = acc[mt][nt][h * 2 + 1] * alpha + b1;
                if (relu2) { v0 = fmaxf(v0, 0.f); v0 *= v0;
                             v1 = fmaxf(v1, 0.f); v1 *= v1; }
                if (resid) {
                    float2 rr = *reinterpret_cast<const float2*>(resid + (long)gr * N + gc);
                    v0 += rr.x; v1 += rr.y;
                }
                if (packout) {
                    __nv_bfloat16* P = reinterpret_cast<__nv_bfloat16*>(C);
                    long base = (long)gr * N + gc;
                    __nv_bfloat162 hp, lp;
                    split2(v0, v1, hp, lp);
                    *reinterpret_cast<__nv_bfloat162*>(P + base)        = hp;
                    *reinterpret_cast<__nv_bfloat162*>(P + base + pOfs) = lp;
                } else {
                    *reinterpret_cast<float2*>(C + (long)gr * N + gc) = make_float2(v0, v1);
                }
            }
        }
    }
}

// ---------------------------------------------------------------------------
// packers / small fills
// ---------------------------------------------------------------------------
__global__ void __launch_bounds__(256) split_pack_pl(
    const float* __restrict__ src, __nv_bfloat16* __restrict__ dst,
    long total2, long planeOfs)
{
    long i = (long)blockIdx.x * 256 + threadIdx.x;
    if (i >= total2) return;
    long e = i << 1;
    float2 x = *reinterpret_cast<const float2*>(src + e);
    __nv_bfloat162 hp, lp;
    split2(x.x, x.y, hp, lp);
    *reinterpret_cast<__nv_bfloat162*>(dst + e)            = hp;
    *reinterpret_cast<__nv_bfloat162*>(dst + planeOfs + e) = lp;
}

__global__ void __launch_bounds__(256) fill_b3(
    const float* __restrict__ vb, float* __restrict__ b3)
{
    int i = blockIdx.x * 256 + threadIdx.x;
    if (i < 3 * Dm) b3[i] = (i < 2 * Dm) ? 0.f : vb[i - 2 * Dm];
}

__global__ void __launch_bounds__(128) fill_qkb(
    const float* __restrict__ qb, const float* __restrict__ kb, float* __restrict__ o)
{
    int i = threadIdx.x;
    o[i] = (i < 64) ? qb[i] : kb[i - 64];
}

// split fused qk buffer -> pQ (A planes) and pK (B planes)
__global__ void __launch_bounds__(256) pack_qk(
    const float* __restrict__ qk, __nv_bfloat16* __restrict__ pQ,
    __nv_bfloat16* __restrict__ pK, long planeOfs)
{
    long i2 = (long)blockIdx.x * 256 + threadIdx.x;
    long idx = i2 << 1;
    if (idx >= (long)NT * Am) return;
    long row = idx >> 6;
    int  c = (int)(idx & 63);
    float2 qv = *reinterpret_cast<const float2*>(qk + row * 128 + c);
    float2 kv = *reinterpret_cast<const float2*>(qk + row * 128 + 64 + c);
    __nv_bfloat162 hp, lp;
    long e = row * Am + c;
    split2(qv.x, qv.y, hp, lp);
    *reinterpret_cast<__nv_bfloat162*>(pQ + e)            = hp;
    *reinterpret_cast<__nv_bfloat162*>(pQ + planeOfs + e) = lp;
    split2(kv.x, kv.y, hp, lp);
    *reinterpret_cast<__nv_bfloat162*>(pK + e)            = hp;
    *reinterpret_cast<__nv_bfloat162*>(pK + planeOfs + e) = lp;
}

// ---------------------------------------------------------------------------
// rmsnorm: fp32 out + optional hi/lo plane out
// ---------------------------------------------------------------------------
__global__ void __launch_bounds__(256) rmsnorm_k(
    const float* __restrict__ x, const float* __restrict__ w,
    float* __restrict__ out, __nv_bfloat16* __restrict__ pk, long planeOfs)
{
    int row = blockIdx.x;
    const float* xr = x + (long)row * Dm;
    int tid = threadIdx.x;
    float ss = 0.f;
    #pragma unroll
    for (int d = tid; d < Dm; d += 256) { float v = xr[d]; ss += v * v; }
    __shared__ float red[256];
    red[tid] = ss; __syncthreads();
    for (int o = 128; o; o >>= 1) {
        if (tid < o) red[tid] += red[tid + o];
        __syncthreads();
    }
    float scale = 1.f / (sqrtf(red[0] * (1.f / Dm)) + 1e-8f);
    #pragma unroll
    for (int d = tid; d < Dm; d += 256) {
        float v = w[d] * xr[d] * scale;
        long e = (long)row * Dm + d;
        out[e] = v;
        if (pk) {
            __nv_bfloat16 h = __float2bfloat16_rn(v);
            __nv_bfloat16 l = __float2bfloat16_rn(v - __bfloat162float(h));
            pk[e] = h; pk[e + planeOfs] = l;
        }
    }
}

// ---------------------------------------------------------------------------
// token-shift mixes -> two hi/lo-plane packed A operands
// ---------------------------------------------------------------------------
__global__ void __launch_bounds__(256) mix2pack_k(
    const float* __restrict__ xn, const float* __restrict__ m1,
    const float* __restrict__ m2,
    __nv_bfloat16* __restrict__ p1, __nv_bfloat16* __restrict__ p2, long planeOfs)
{
    long pi2 = (long)blockIdx.x * 256 + threadIdx.x;
    long i = pi2 << 1;
    int d = (int)(i & (Dm - 1));
    int s = (int)((i >> 10) & (Sm - 1));
    long prev = s ? (i - Dm) : i;
    float2 cur = *reinterpret_cast<const float2*>(xn + i);
    float2 prv = *reinterpret_cast<const float2*>(xn + prev);
    float a0 = m1[d], a1 = m1[d + 1];
    float b0 = m2[d], b1 = m2[d + 1];
    float o10 = cur.x * a0 + prv.x * (1.f - a0);
    float o11 = cur.y * a1 + prv.y * (1.f - a1);
    float o20 = cur.x * b0 + prv.x * (1.f - b0);
    float o21 = cur.y * b1 + prv.y * (1.f - b1);
    __nv_bfloat162 hp, lp;
    split2(o10, o11, hp, lp);
    *reinterpret_cast<__nv_bfloat162*>(p1 + i)            = hp;
    *reinterpret_cast<__nv_bfloat162*>(p1 + planeOfs + i) = lp;
    split2(o20, o21, hp, lp);
    *reinterpret_cast<__nv_bfloat162*>(p2 + i)            = hp;
    *reinterpret_cast<__nv_bfloat162*>(p2 + planeOfs + i) = lp;
}

// ---------------------------------------------------------------------------
// top-32 (owner-rescan) + softmax + V-gather -> hi/lo planes
// ---------------------------------------------------------------------------
__global__ void __launch_bounds__(128) topk_attn_k(
    const float* __restrict__ Sc, const float* __restrict__ Vsa,
    __nv_bfloat16* __restrict__ OutP, long planeOfs)
{
    int q = blockIdx.x;
    int b = q >> 12;
    const float* srow = Sc + (long)q * Sm;

    __shared__ float topv[KTOP];
    __shared__ int   topi[KTOP];
    __shared__ float wmv[4];
    __shared__ int   wiv[4];
    __shared__ int   sel;
    __shared__ float p[KTOP];

    const int tid  = threadIdx.x;
    const int lane = tid & 31;
    const int wrp  = tid >> 5;

    float sv[32];
    #pragma unroll
    for (int i = 0; i < 32; i++) sv[i] = srow[tid + (i << 7)];

    float best = -INFINITY; int bloc = 0;
    #pragma unroll
    for (int i = 0; i < 32; i++)
        if (sv[i] > best) { best = sv[i]; bloc = i; }

    for (int it = 0; it < KTOP; it++) {
        float cb = best;
        int   ci = tid + (bloc << 7);
        #pragma unroll
        for (int o = 16; o; o >>= 1) {
            float ov = __shfl_down_sync(0xffffffffu, cb, o);
            int   oi = __shfl_down_sync(0xffffffffu, ci, o);
            if (ov > cb || (ov == cb && oi < ci)) { cb = ov; ci = oi; }
        }
        if (lane == 0) { wmv[wrp] = cb; wiv[wrp] = ci; }
        __syncthreads();
        if (tid == 0) {
            float bb = wmv[0]; int bj = wiv[0];
            #pragma unroll
            for (int w2 = 1; w2 < 4; w2++)
                if (wmv[w2] > bb || (wmv[w2] == bb && wiv[w2] < bj)) { bb = wmv[w2]; bj = wiv[w2]; }
            topv[it] = bb; topi[it] = bj; sel = bj;
        }
        __syncthreads();
        int bj = sel;
        if ((bj & 127) == tid) {
            sv[bj >> 7] = -INFINITY;
            best = -INFINITY; bloc = 0;
            #pragma unroll
            for (int i = 0; i < 32; i++)
                if (sv[i] > best) { best = sv[i]; bloc = i; }
        }
        __syncthreads();
    }

    if (tid == 0) {
        float mx = topv[0], Z = 0.f;
        #pragma unroll
        for (int i2 = 0; i2 < KTOP; i2++) { float e = expf(topv[i2] - mx); p[i2] = e; Z += e; }
        float iz = 1.f / Z;
        #pragma unroll
        for (int i2 = 0; i2 < KTOP; i2++) p[i2] *= iz;
    }
    __syncthreads();

    const float* Vb = Vsa + (long)b * Sm * Dm;
    for (int d = tid; d < Dm; d += 128) {
        float acc = 0.f;
        #pragma unroll
        for (int i2 = 0; i2 < KTOP; i2++)
            acc += p[i2] * Vb[(long)topi[i2] * Dm + d];
        __nv_bfloat16 h = __float2bfloat16_rn(acc);
        __nv_bfloat16 l = __float2bfloat16_rn(acc - __bfloat162float(h));
        long e = (long)q * Dm + d;
        OutP[e] = h; OutP[e + planeOfs] = l;
    }
}

// ---------------------------------------------------------------------------
// gates
// ---------------------------------------------------------------------------
__global__ void __launch_bounds__(256) rkvpack_k(
    const float* __restrict__ r, const float* __restrict__ ao,
    const float* __restrict__ v, __nv_bfloat16* __restrict__ p1, long planeOfs)
{
    long pi2 = (long)blockIdx.x * 256 + threadIdx.x;
    long i = pi2 << 1;
    float2 rr = *reinterpret_cast<const float2*>(r + i);
    float2 aa = *reinterpret_cast<const float2*>(ao + i);
    float2 vv = *reinterpret_cast<const float2*>(v + i);
    float o0 = (1.f / (1.f + expf(-rr.x))) * (aa.x + vv.x);
    float o1 = (1.f / (1.f + expf(-rr.y))) * (aa.y + vv.y);
    __nv_bfloat162 hp, lp;
    split2(o0, o1, hp, lp);
    *reinterpret_cast<__nv_bfloat162*>(p1 + i)            = hp;
    *reinterpret_cast<__nv_bfloat162*>(p1 + planeOfs + i) = lp;
}

__global__ void __launch_bounds__(256) final_k(
    const float* __restrict__ x1, const float* __restrict__ r2,
    const float* __restrict__ kv, float* __restrict__ o)
{
    long i = (long)blockIdx.x * 256 + threadIdx.x;
    float sig = 1.f / (1.f + expf(-r2[i]));
    o[i] = x1[i] + sig * kv[i];
}

// ---------------------------------------------------------------------------
// launcher
// ---------------------------------------------------------------------------
extern "C" void kernel_launch(void* const* d_in, const int* in_sizes, int n_in,
                              void* d_out, int out_size)
{
    const float* x           = (const float*)d_in[0];
    const float* norm1_w     = (const float*)d_in[1];
    const float* tm_mix_v    = (const float*)d_in[3];
    const float* tm_mix_r    = (const float*)d_in[4];
    // d_in[2]=tm_mix_k, d_in[5]=tm_key_w: dead in reference
    const float* tm_value_w  = (const float*)d_in[6];
    const float* tm_recept_w = (const float*)d_in[7];
    const float* tm_out_w    = (const float*)d_in[8];
    const float* sa_q_w      = (const float*)d_in[9];
    const float* sa_q_b      = (const float*)d_in[10];
    const float* sa_k_w      = (const float*)d_in[11];
    const float* sa_k_b      = (const float*)d_in[12];
    const float* sa_v_w      = (const float*)d_in[13];
    const float* sa_v_b      = (const float*)d_in[14];
    const float* sa_o_w      = (const float*)d_in[15];
    const float* sa_o_b      = (const float*)d_in[16];
    const float* norm2_w     = (const float*)d_in[17];
    const float* cm_mix_k    = (const float*)d_in[18];
    const float* cm_mix_r    = (const float*)d_in[19];
    const float* cm_key_w    = (const float*)d_in[20];
    const float* cm_recept_w = (const float*)d_in[21];
    const float* cm_value_w  = (const float*)d_in[22];
    float* out = (float*)d_out;

    float *xn, *vrv, *ao, *x1, *qk, *big, *b3, *qkb;
    __nv_bfloat16 *pAct, *pBIG, *pQ, *pK, *wpk, *wqk;
    cudaGetSymbolAddress((void**)&xn,   g_xn);
    cudaGetSymbolAddress((void**)&vrv,  g_vrv);
    cudaGetSymbolAddress((void**)&ao,   g_ao);
    cudaGetSymbolAddress((void**)&x1,   g_x1);
    cudaGetSymbolAddress((void**)&qk,   g_qk);
    cudaGetSymbolAddress((void**)&big,  g_big);
    cudaGetSymbolAddress((void**)&b3,   g_b3);
    cudaGetSymbolAddress((void**)&qkb,  g_qkb);
    cudaGetSymbolAddress((void**)&pAct, g_pAct);
    cudaGetSymbolAddress((void**)&pBIG, g_pBIG);
    cudaGetSymbolAddress((void**)&pQ,   g_pQ);
    cudaGetSymbolAddress((void**)&pK,   g_pK);
    cudaGetSymbolAddress((void**)&wpk,  g_wpk);
    cudaGetSymbolAddress((void**)&wqk,  g_wqk);

    cudaFuncSetAttribute(mma_gemm<256>, cudaFuncAttributeMaxDynamicSharedMemorySize, 196608);
    cudaFuncSetAttribute(mma_gemm<128>, cudaFuncAttributeMaxDynamicSharedMemorySize, 131072);

    const long ofsD  = (long)NT * Dm;            // activation plane size
    const long ofsDI = (long)NT * DIm;
    const long ofsA  = (long)NT * Am;
    const long slot  = 2 * ofsD;                 // z-slot stride in pAct
    const long wslot = 2L * Dm * Dm;             // z-slot stride in wpk
    __nv_bfloat16* pS0 = pAct;                   // mix1 / att / cm mix1
    __nv_bfloat16* pS1 = pAct + slot;            // mix2 / rkv / cm mix2
    __nv_bfloat16* pS2 = pAct + 2 * slot;        // xn packed

    const dim3 gD (Dm / 256,  NT / 128);          // (4, 64)
    const dim3 gD3(Dm / 256,  NT / 128, 3);       // batched v/r/vsa
    const dim3 gDI(DIm / 256, NT / 128);          // (16, 64)
    const dim3 gS (Sm / 256,  Sm / 128, Bb);      // (16, 32, 2)
    const dim3 gQK(1, NT / 128);                  // fused q/k, BN=128
    const int  pairBlocks = NT * Dm / 512;
    const int  wDDblocks  = (int)((Dm * (long)Dm / 2 + 255) / 256);
    const int  wDIblocks  = (int)((DIm * (long)Dm / 2 + 255) / 256);

    // ---- time mix ----
    rmsnorm_k<<<NT, 256>>>(x, norm1_w, xn, pS2, ofsD);
    mix2pack_k<<<pairBlocks, 256>>>(xn, tm_mix_v, tm_mix_r, pS0, pS1, ofsD);

    // batched v / r / vsa
    split_pack_pl<<<wDDblocks, 256>>>(tm_value_w,  wpk,              Dm * (long)Dm / 2, (long)Dm * Dm);
    split_pack_pl<<<wDDblocks, 256>>>(tm_recept_w, wpk + wslot,      Dm * (long)Dm / 2, (long)Dm * Dm);
    split_pack_pl<<<wDDblocks, 256>>>(sa_v_w,      wpk + 2 * wslot,  Dm * (long)Dm / 2, (long)Dm * Dm);
    fill_b3<<<(3 * Dm + 255) / 256, 256>>>(sa_v_b, b3);
    mma_gemm<256><<<gD3, 256, 196608>>>(pAct, ofsD, wpk, (long)Dm * Dm, vrv, Dm, Dm,
                                        slot, wslot, ofsD, b3, Dm, nullptr, 1.f, 0, 0, 0);
    float* v   = vrv;
    float* r   = vrv + ofsD;
    float* vsa = vrv + 2 * ofsD;

    // fused q/k projection on tensor path (BN=128)
    split_pack_pl<<<(int)((64L * Dm / 2 + 255) / 256), 256>>>(sa_q_w, wqk,            64L * Dm / 2, 128L * Dm);
    split_pack_pl<<<(int)((64L * Dm / 2 + 255) / 256), 256>>>(sa_k_w, wqk + 64 * Dm,  64L * Dm / 2, 128L * Dm);
    fill_qkb<<<1, 128>>>(sa_q_b, sa_k_b, qkb);
    mma_gemm<128><<<gQK, 256, 131072>>>(pS2, ofsD, wqk, 128L * Dm, qk, 128, Dm,
                                        0, 0, 0, qkb, 0, nullptr, 1.f, 0, 0, 0);
    pack_qk<<<(int)((ofsA / 2 + 255) / 256), 256>>>(qk, pQ, pK, ofsA);

    // scores
    mma_gemm<256><<<gS, 256, 196608>>>(pQ, ofsA, pK, ofsA, big, Sm, Am,
                                       (long)Sm * Am, (long)Sm * Am, (long)Sm * Sm,
                                       nullptr, 0, nullptr, 0.125f, 0, 0, 0);

    topk_attn_k<<<NT, 128>>>(big, vsa, pS0, ofsD);

    split_pack_pl<<<wDDblocks, 256>>>(sa_o_w, wpk, Dm * (long)Dm / 2, (long)Dm * Dm);
    mma_gemm<256><<<gD, 256, 196608>>>(pS0, ofsD, wpk, (long)Dm * Dm, ao, Dm, Dm,
                                       0, 0, 0, sa_o_b, 0, nullptr, 1.f, 0, 0, 0);

    rkvpack_k<<<pairBlocks, 256>>>(r, ao, v, pS1, ofsD);

    split_pack_pl<<<wDDblocks, 256>>>(tm_out_w, wpk, Dm * (long)Dm / 2, (long)Dm * Dm);
    mma_gemm<256><<<gD, 256, 196608>>>(pS1, ofsD, wpk, (long)Dm * Dm, x1, Dm, Dm,
                                       0, 0, 0, nullptr, 0, x, 1.f, 0, 0, 0);

    // ---- channel mix ----
    rmsnorm_k<<<NT, 256>>>(x1, norm2_w, xn, nullptr, 0);
    mix2pack_k<<<pairBlocks, 256>>>(xn, cm_mix_k, cm_mix_r, pS0, pS1, ofsD);

    split_pack_pl<<<wDIblocks, 256>>>(cm_key_w, wpk, DIm * (long)Dm / 2, (long)DIm * Dm);
    mma_gemm<256><<<gDI, 256, 196608>>>(pS0, ofsD, wpk, (long)DIm * Dm, (float*)pBIG, DIm, Dm,
                                        0, 0, 0, nullptr, 0, nullptr, 1.f, 1, 1, ofsDI);

    split_pack_pl<<<wDDblocks, 256>>>(cm_recept_w, wpk, Dm * (long)Dm / 2, (long)Dm * Dm);
    mma_gemm<256><<<gD, 256, 196608>>>(pS1, ofsD, wpk, (long)Dm * Dm, r, Dm, Dm,
                                       0, 0, 0, nullptr, 0, nullptr, 1.f, 0, 0, 0);

    split_pack_pl<<<wDIblocks, 256>>>(cm_value_w, wpk, DIm * (long)Dm / 2, (long)DIm * Dm);
    mma_gemm<256><<<gD, 256, 196608>>>(pBIG, ofsDI, wpk, (long)DIm * Dm, v, Dm, DIm,
                                       0, 0, 0, nullptr, 0, nullptr, 1.f, 0, 0, 0);

    final_k<<<2 * pairBlocks, 256>>>(x1, r, v, out);
}